// round 1
// baseline (speedup 1.0000x reference)
#include <cuda_runtime.h>

#define D_   1024
#define H_   16
#define HD_  64
#define B_   2
#define S_   2048
#define M_   (B_ * S_)          // 4096

// ---------------- scratch (device globals; no allocation allowed) ----------
__device__ float g_Q[(size_t)M_ * D_];     // [B,H,S,HD]
__device__ float g_K[(size_t)M_ * D_];
__device__ float g_V[(size_t)M_ * D_];
__device__ float g_ctx[(size_t)M_ * D_];   // [B,S,D]

// ---------------------------------------------------------------------------
// GEMM: C[m, e] = sum_k A[m, k] * W[e, k] + bias[e]
// A: [M_, D_], W: [D_, D_] (row-major, so this is x @ W^T like nn.Linear)
// split_heads: write to [B,H,S,HD] layout instead of [M, D_]
// Tiles: BM=64, BN=64, BK=16; 256 threads; 4x4 register tile per thread.
// ---------------------------------------------------------------------------
__global__ __launch_bounds__(256) void gemm_kernel(
    const float* __restrict__ A,
    const float* __restrict__ W,
    const float* __restrict__ bias,
    float* __restrict__ out,
    int split_heads)
{
    __shared__ __align__(16) float As[16][68];   // [k][m], 68-stride: conflict-free
    __shared__ __align__(16) float Ws[16][68];   // [k][n]

    const int t  = threadIdx.x;
    const int lr = t >> 2;           // 0..63 row within tile (for loads)
    const int lk = (t & 3) << 2;     // k offset 0,4,8,12
    const int m0 = blockIdx.y << 6;
    const int n0 = blockIdx.x << 6;
    const int ty = t >> 4;           // 0..15
    const int tx = t & 15;           // 0..15

    const float* Ap = A + (size_t)(m0 + lr) * D_ + lk;
    const float* Wp = W + (size_t)(n0 + lr) * D_ + lk;

    float acc[4][4];
#pragma unroll
    for (int i = 0; i < 4; i++)
#pragma unroll
        for (int j = 0; j < 4; j++) acc[i][j] = 0.0f;

    for (int k0 = 0; k0 < D_; k0 += 16) {
        float4 a = *(const float4*)(Ap + k0);
        float4 w = *(const float4*)(Wp + k0);
        __syncthreads();
        As[lk + 0][lr] = a.x; As[lk + 1][lr] = a.y;
        As[lk + 2][lr] = a.z; As[lk + 3][lr] = a.w;
        Ws[lk + 0][lr] = w.x; Ws[lk + 1][lr] = w.y;
        Ws[lk + 2][lr] = w.z; Ws[lk + 3][lr] = w.w;
        __syncthreads();
#pragma unroll
        for (int k = 0; k < 16; k++) {
            float4 av = *(const float4*)&As[k][ty << 2];
            float4 wv = *(const float4*)&Ws[k][tx << 2];
            float ar[4] = {av.x, av.y, av.z, av.w};
            float wr[4] = {wv.x, wv.y, wv.z, wv.w};
#pragma unroll
            for (int i = 0; i < 4; i++)
#pragma unroll
                for (int j = 0; j < 4; j++)
                    acc[i][j] += ar[i] * wr[j];
        }
    }

#pragma unroll
    for (int i = 0; i < 4; i++) {
        const int m = m0 + (ty << 2) + i;
        const int b = m >> 11;        // / S_
        const int s = m & (S_ - 1);
#pragma unroll
        for (int j = 0; j < 4; j++) {
            const int e = n0 + (tx << 2) + j;
            const float v = acc[i][j] + bias[e];
            if (split_heads) {
                const int h  = e >> 6;
                const int hd = e & 63;
                out[(((size_t)(b * H_ + h) * S_ + s) << 6) + hd] = v;
            } else {
                out[(size_t)m * D_ + e] = v;
            }
        }
    }
}

// ---------------------------------------------------------------------------
// Flash attention: per block = one 64-row Q tile of one (b,h).
// Q,K,V: [B*H, S, 64].  ctx out: [B, S, D] (heads re-interleaved).
// 256 threads, (ty,tx) = 16x16; each thread owns 4 q-rows x 4 cols.
// SMEM: Qt[d][r], Kt[d][c] (transposed, conflict-free float4 along r/c),
//       Vs[c][d], Ps[r][c]; all stride 68.
// ---------------------------------------------------------------------------
#define FL_SMEM (4 * 64 * 68 * 4)

__global__ __launch_bounds__(256) void flash_kernel(
    const float* __restrict__ Q,
    const float* __restrict__ K,
    const float* __restrict__ V,
    float* __restrict__ ctx)
{
    extern __shared__ __align__(16) float sm[];
    float* Qt = sm;                  // [64][68] : Qt[d*68 + r]
    float* Kt = sm + 64 * 68;        // [64][68] : Kt[d*68 + c]
    float* Vs = sm + 2 * 64 * 68;    // [64][68] : Vs[c*68 + d]
    float* Ps = sm + 3 * 64 * 68;    // [64][68] : Ps[r*68 + c]

    const int t  = threadIdx.x;
    const int ty = t >> 4;           // q-row group
    const int tx = t & 15;           // col group
    const int bh = blockIdx.y;
    const int q0 = blockIdx.x << 6;

    const float* Qb = Q + (size_t)bh * S_ * HD_;
    const float* Kb = K + (size_t)bh * S_ * HD_;
    const float* Vb = V + (size_t)bh * S_ * HD_;

    const float sm_scale = 0.125f;   // 1/sqrt(64)

    // Load Q tile, transposed + pre-scaled
    for (int i = t; i < 64 * 64; i += 256) {
        const int r = i >> 6, d = i & 63;
        Qt[d * 68 + r] = Qb[(size_t)(q0 + r) * HD_ + d] * sm_scale;
    }

    float m_i[4], l_i[4], acc[4][4];
#pragma unroll
    for (int i = 0; i < 4; i++) {
        m_i[i] = -1e30f;
        l_i[i] = 0.0f;
#pragma unroll
        for (int j = 0; j < 4; j++) acc[i][j] = 0.0f;
    }

    for (int kt = 0; kt < S_ / 64; kt++) {
        const int k0 = kt << 6;
        __syncthreads();   // prev P*V finished before overwriting K/V
        for (int i = t; i < 64 * 64; i += 256) {
            const int c = i >> 6, d = i & 63;
            Kt[d * 68 + c] = Kb[(size_t)(k0 + c) * HD_ + d];
        }
        for (int i = t << 2; i < 64 * 64; i += 1024) {
            const int c = i >> 6, d = i & 63;
            *(float4*)&Vs[c * 68 + d] = *(const float4*)&Vb[(size_t)(k0 + c) * HD_ + d];
        }
        __syncthreads();

        // ---- scores: sc[i][j] = (Q row ty*4+i) . (K row tx*4+j), pre-scaled
        float sc[4][4];
#pragma unroll
        for (int i = 0; i < 4; i++)
#pragma unroll
            for (int j = 0; j < 4; j++) sc[i][j] = 0.0f;

#pragma unroll 4
        for (int d = 0; d < 64; d++) {
            float4 qv = *(const float4*)&Qt[d * 68 + (ty << 2)];
            float4 kv = *(const float4*)&Kt[d * 68 + (tx << 2)];
            float qr[4] = {qv.x, qv.y, qv.z, qv.w};
            float kr[4] = {kv.x, kv.y, kv.z, kv.w};
#pragma unroll
            for (int i = 0; i < 4; i++)
#pragma unroll
                for (int j = 0; j < 4; j++)
                    sc[i][j] += qr[i] * kr[j];
        }

        // ---- online softmax (row stats across the 16 tx threads of each row)
#pragma unroll
        for (int i = 0; i < 4; i++) {
            float mx = fmaxf(fmaxf(sc[i][0], sc[i][1]), fmaxf(sc[i][2], sc[i][3]));
#pragma unroll
            for (int o = 8; o > 0; o >>= 1)
                mx = fmaxf(mx, __shfl_xor_sync(0xffffffffu, mx, o));
            const float mnew = fmaxf(m_i[i], mx);
            const float corr = __expf(m_i[i] - mnew);
            m_i[i] = mnew;
            float rs = 0.0f;
#pragma unroll
            for (int j = 0; j < 4; j++) {
                sc[i][j] = __expf(sc[i][j] - mnew);
                rs += sc[i][j];
            }
#pragma unroll
            for (int o = 8; o > 0; o >>= 1)
                rs += __shfl_xor_sync(0xffffffffu, rs, o);
            l_i[i] = l_i[i] * corr + rs;
#pragma unroll
            for (int j = 0; j < 4; j++) acc[i][j] *= corr;
            *(float4*)&Ps[((ty << 2) + i) * 68 + (tx << 2)] =
                make_float4(sc[i][0], sc[i][1], sc[i][2], sc[i][3]);
        }
        __syncthreads();

        // ---- acc += P @ V  (thread owns rows ty*4+i, d-cols tx*4+j)
#pragma unroll 4
        for (int c = 0; c < 64; c++) {
            float4 vv = *(const float4*)&Vs[c * 68 + (tx << 2)];
            float vr[4] = {vv.x, vv.y, vv.z, vv.w};
            float pv[4];
#pragma unroll
            for (int i = 0; i < 4; i++)
                pv[i] = Ps[((ty << 2) + i) * 68 + c];
#pragma unroll
            for (int i = 0; i < 4; i++)
#pragma unroll
                for (int j = 0; j < 4; j++)
                    acc[i][j] += pv[i] * vr[j];
        }
    }

    // ---- write ctx in [B,S,D] layout (heads interleaved back)
    const int b = bh >> 4;     // / H_
    const int h = bh & 15;
#pragma unroll
    for (int i = 0; i < 4; i++) {
        const int s = q0 + (ty << 2) + i;
        const float inv = 1.0f / l_i[i];
        float4 o = make_float4(acc[i][0] * inv, acc[i][1] * inv,
                               acc[i][2] * inv, acc[i][3] * inv);
        *(float4*)&ctx[(size_t)(b * S_ + s) * D_ + (h << 6) + (tx << 2)] = o;
    }
}

// ---------------------------------------------------------------------------
extern "C" void kernel_launch(void* const* d_in, const int* in_sizes, int n_in,
                              void* d_out, int out_size)
{
    const float* query = (const float*)d_in[0];
    const float* key   = (const float*)d_in[1];
    const float* value = (const float*)d_in[2];
    const float* Wq    = (const float*)d_in[3];
    const float* bq    = (const float*)d_in[4];
    const float* Wk    = (const float*)d_in[5];
    const float* bk    = (const float*)d_in[6];
    const float* Wv    = (const float*)d_in[7];
    const float* bv    = (const float*)d_in[8];
    const float* Wo    = (const float*)d_in[9];
    const float* bo    = (const float*)d_in[10];

    float *Qp, *Kp, *Vp, *Cp;
    cudaGetSymbolAddress((void**)&Qp, g_Q);
    cudaGetSymbolAddress((void**)&Kp, g_K);
    cudaGetSymbolAddress((void**)&Vp, g_V);
    cudaGetSymbolAddress((void**)&Cp, g_ctx);

    cudaFuncSetAttribute(flash_kernel,
                         cudaFuncAttributeMaxDynamicSharedMemorySize, FL_SMEM);

    const dim3 gg(D_ / 64, M_ / 64);   // (16, 64)
    gemm_kernel<<<gg, 256>>>(query, Wq, bq, Qp, 1);
    gemm_kernel<<<gg, 256>>>(key,   Wk, bk, Kp, 1);
    gemm_kernel<<<gg, 256>>>(value, Wv, bv, Vp, 1);

    flash_kernel<<<dim3(S_ / 64, B_ * H_), 256, FL_SMEM>>>(Qp, Kp, Vp, Cp);

    gemm_kernel<<<gg, 256>>>(Cp, Wo, bo, (float*)d_out, 0);
}

// round 2
// speedup vs baseline: 2.1778x; 2.1778x over previous
#include <cuda_runtime.h>

#define D_   1024
#define H_   16
#define HD_  64
#define B_   2
#define S_   2048
#define M_   (B_ * S_)          // 4096

// ---------------- scratch (device globals; no allocation allowed) ----------
__device__ float g_Q[(size_t)M_ * D_];     // [B,H,S,HD]
__device__ float g_K[(size_t)M_ * D_];
__device__ float g_V[(size_t)M_ * D_];
__device__ float g_ctx[(size_t)M_ * D_];   // [B,S,D]

// ---------------------------------------------------------------------------
// helpers
// ---------------------------------------------------------------------------
__device__ __forceinline__ unsigned f2tf(float f) {
    unsigned u;
    asm("cvt.rna.tf32.f32 %0, %1;" : "=r"(u) : "f"(f));
    return u;
}

__device__ __forceinline__ void mma_tf32(float c[4], const unsigned a[4], const unsigned b[2]) {
    asm volatile(
        "mma.sync.aligned.m16n8k8.row.col.f32.tf32.tf32.f32 "
        "{%0,%1,%2,%3}, {%4,%5,%6,%7}, {%8,%9}, {%0,%1,%2,%3};\n"
        : "+f"(c[0]), "+f"(c[1]), "+f"(c[2]), "+f"(c[3])
        : "r"(a[0]), "r"(a[1]), "r"(a[2]), "r"(a[3]), "r"(b[0]), "r"(b[1]));
}

// ---------------------------------------------------------------------------
// GEMM (tf32 tensor cores): C[m,e] = A[m,:] . W[e,:] + bias[e]
// BM=BN=128, BK=16. 256 threads = 8 warps (4x2), warp tile 32x64.
// SMEM holds tf32 bits, row stride 20 (20 mod 32 = 20; frag reads hit
// (20*r + k) % 32 with r in {gp..gp+..}: 4-stride pattern -> conflict-free).
// ---------------------------------------------------------------------------
__global__ __launch_bounds__(256) void gemm_tf32_kernel(
    const float* __restrict__ A,
    const float* __restrict__ W,
    const float* __restrict__ bias,
    float* __restrict__ out,
    int split_heads)
{
    __shared__ __align__(16) unsigned As[128 * 20];
    __shared__ __align__(16) unsigned Bs[128 * 20];

    const int t    = threadIdx.x;
    const int lane = t & 31;
    const int w    = t >> 5;
    const int wr   = w >> 1;          // 0..3 : warp m offset wr*32
    const int wc   = w & 1;           // 0..1 : warp n offset wc*64
    const int gp   = lane >> 2;       // 0..7
    const int tg   = lane & 3;        // 0..3

    const int m0 = blockIdx.y << 7;
    const int n0 = blockIdx.x << 7;

    // gmem load mapping: thread t loads row (t>>1), 8 consecutive floats at
    // k offset (t&1)*8 of each 16-wide k-slab.
    const int lrow = t >> 1;
    const int lk8  = (t & 1) << 3;
    const float* Ap = A + (size_t)(m0 + lrow) * D_ + lk8;
    const float* Wp = W + (size_t)(n0 + lrow) * D_ + lk8;

    float acc[2][8][4];
#pragma unroll
    for (int mi = 0; mi < 2; mi++)
#pragma unroll
        for (int nj = 0; nj < 8; nj++)
#pragma unroll
            for (int q = 0; q < 4; q++) acc[mi][nj][q] = 0.0f;

    float4 pa0 = *(const float4*)(Ap);
    float4 pa1 = *(const float4*)(Ap + 4);
    float4 pb0 = *(const float4*)(Wp);
    float4 pb1 = *(const float4*)(Wp + 4);

    for (int k0 = 0; k0 < D_ / 16; k0++) {
        __syncthreads();
        {
            uint4 ua0 = make_uint4(f2tf(pa0.x), f2tf(pa0.y), f2tf(pa0.z), f2tf(pa0.w));
            uint4 ua1 = make_uint4(f2tf(pa1.x), f2tf(pa1.y), f2tf(pa1.z), f2tf(pa1.w));
            uint4 ub0 = make_uint4(f2tf(pb0.x), f2tf(pb0.y), f2tf(pb0.z), f2tf(pb0.w));
            uint4 ub1 = make_uint4(f2tf(pb1.x), f2tf(pb1.y), f2tf(pb1.z), f2tf(pb1.w));
            *(uint4*)&As[lrow * 20 + lk8]     = ua0;
            *(uint4*)&As[lrow * 20 + lk8 + 4] = ua1;
            *(uint4*)&Bs[lrow * 20 + lk8]     = ub0;
            *(uint4*)&Bs[lrow * 20 + lk8 + 4] = ub1;
        }
        __syncthreads();

        if (k0 < D_ / 16 - 1) {
            const int off = (k0 + 1) * 16;
            pa0 = *(const float4*)(Ap + off);
            pa1 = *(const float4*)(Ap + off + 4);
            pb0 = *(const float4*)(Wp + off);
            pb1 = *(const float4*)(Wp + off + 4);
        }

#pragma unroll
        for (int ks = 0; ks < 2; ks++) {
            unsigned a[2][4];
#pragma unroll
            for (int mi = 0; mi < 2; mi++) {
                const int r = wr * 32 + mi * 16 + gp;
                a[mi][0] = As[r * 20 + ks * 8 + tg];
                a[mi][1] = As[(r + 8) * 20 + ks * 8 + tg];
                a[mi][2] = As[r * 20 + ks * 8 + tg + 4];
                a[mi][3] = As[(r + 8) * 20 + ks * 8 + tg + 4];
            }
#pragma unroll
            for (int nj = 0; nj < 8; nj++) {
                unsigned b[2];
                const int n = wc * 64 + nj * 8 + gp;
                b[0] = Bs[n * 20 + ks * 8 + tg];
                b[1] = Bs[n * 20 + ks * 8 + tg + 4];
#pragma unroll
                for (int mi = 0; mi < 2; mi++)
                    mma_tf32(acc[mi][nj], a[mi], b);
            }
        }
    }

    // epilogue
#pragma unroll
    for (int mi = 0; mi < 2; mi++) {
#pragma unroll
        for (int h = 0; h < 2; h++) {
            const int m = m0 + wr * 32 + mi * 16 + gp + h * 8;
            const int b_ = m >> 11;
            const int s  = m & (S_ - 1);
#pragma unroll
            for (int nj = 0; nj < 8; nj++) {
                const int e = n0 + wc * 64 + nj * 8 + 2 * tg;
                float2 v;
                v.x = acc[mi][nj][2 * h]     + bias[e];
                v.y = acc[mi][nj][2 * h + 1] + bias[e + 1];
                if (split_heads) {
                    const int hh = e >> 6;
                    const int hd = e & 63;
                    *(float2*)&out[(((size_t)(b_ * H_ + hh) * S_ + s) << 6) + hd] = v;
                } else {
                    *(float2*)&out[(size_t)m * D_ + e] = v;
                }
            }
        }
    }
}

// ---------------------------------------------------------------------------
// Flash attention, tf32 tensor cores.
// Block = 128 threads (4 warps), q-tile 64 rows (16 rows/warp), K/V tiles 64.
// SMEM (stride 68, all frag reads conflict-free): Qs[r][k], Ks[c][k],
// Vt[d][c] (transposed), Ps[r][c]. All tf32 bits.
// ---------------------------------------------------------------------------
#define FL_SMEM (4 * 64 * 68 * 4)

__global__ __launch_bounds__(128) void flash_tf32_kernel(
    const float* __restrict__ Q,
    const float* __restrict__ K,
    const float* __restrict__ V,
    float* __restrict__ ctx)
{
    extern __shared__ __align__(16) unsigned sm[];
    unsigned* Qs = sm;                 // [64][68]
    unsigned* Ks = sm + 64 * 68;       // [64][68]
    unsigned* Vt = sm + 2 * 64 * 68;   // [64][68] : Vt[d*68+c]
    unsigned* Ps = sm + 3 * 64 * 68;   // [64][68]

    const int t    = threadIdx.x;
    const int lane = t & 31;
    const int w    = t >> 5;
    const int gp   = lane >> 2;
    const int tg   = lane & 3;
    const int qr0  = w << 4;           // warp's q-row base in tile

    const int bh = blockIdx.y;
    const int q0 = blockIdx.x << 6;

    const float* Qb = Q + (size_t)bh * S_ * HD_;
    const float* Kb = K + (size_t)bh * S_ * HD_;
    const float* Vb = V + (size_t)bh * S_ * HD_;

    const float sm_scale = 0.125f;

    // load Q tile (scaled, tf32-rounded); 64 rows x 16 float4s
    for (int i = t; i < 64 * 16; i += 128) {
        const int r = i >> 4, f = i & 15;
        float4 v = *(const float4*)&Qb[(size_t)(q0 + r) * HD_ + f * 4];
        *(uint4*)&Qs[r * 68 + f * 4] = make_uint4(
            f2tf(v.x * sm_scale), f2tf(v.y * sm_scale),
            f2tf(v.z * sm_scale), f2tf(v.w * sm_scale));
    }

    float o[8][4];
    float m_i[2], l_i[2];
#pragma unroll
    for (int nj = 0; nj < 8; nj++)
#pragma unroll
        for (int q = 0; q < 4; q++) o[nj][q] = 0.0f;
    m_i[0] = m_i[1] = -1e30f;
    l_i[0] = l_i[1] = 0.0f;

    for (int kt = 0; kt < S_ / 64; kt++) {
        const int k0 = kt << 6;
        __syncthreads();   // prev iteration's PV / K reads done
        for (int i = t; i < 64 * 16; i += 128) {
            const int c = i >> 4, f = i & 15;
            float4 v = *(const float4*)&Kb[(size_t)(k0 + c) * HD_ + f * 4];
            *(uint4*)&Ks[c * 68 + f * 4] = make_uint4(
                f2tf(v.x), f2tf(v.y), f2tf(v.z), f2tf(v.w));
        }
        for (int i = t; i < 64 * 16; i += 128) {
            const int c = i >> 4, f = i & 15;
            const int d = f * 4;
            float4 v = *(const float4*)&Vb[(size_t)(k0 + c) * HD_ + d];
            Vt[(d + 0) * 68 + c] = f2tf(v.x);
            Vt[(d + 1) * 68 + c] = f2tf(v.y);
            Vt[(d + 2) * 68 + c] = f2tf(v.z);
            Vt[(d + 3) * 68 + c] = f2tf(v.w);
        }
        __syncthreads();

        // ---- S = Q @ K^T
        float s[8][4];
#pragma unroll
        for (int nj = 0; nj < 8; nj++)
#pragma unroll
            for (int q = 0; q < 4; q++) s[nj][q] = 0.0f;

#pragma unroll
        for (int ks = 0; ks < 8; ks++) {
            unsigned a[4];
            const int r = qr0 + gp;
            a[0] = Qs[r * 68 + ks * 8 + tg];
            a[1] = Qs[(r + 8) * 68 + ks * 8 + tg];
            a[2] = Qs[r * 68 + ks * 8 + tg + 4];
            a[3] = Qs[(r + 8) * 68 + ks * 8 + tg + 4];
#pragma unroll
            for (int nj = 0; nj < 8; nj++) {
                unsigned b[2];
                const int c = nj * 8 + gp;
                b[0] = Ks[c * 68 + ks * 8 + tg];
                b[1] = Ks[c * 68 + ks * 8 + tg + 4];
                mma_tf32(s[nj], a, b);
            }
        }

        // ---- online softmax; rows owned: qr0 + gp + 8h, h in {0,1}
#pragma unroll
        for (int h = 0; h < 2; h++) {
            float mx = -1e30f;
#pragma unroll
            for (int nj = 0; nj < 8; nj++)
                mx = fmaxf(mx, fmaxf(s[nj][2 * h], s[nj][2 * h + 1]));
            mx = fmaxf(mx, __shfl_xor_sync(0xffffffffu, mx, 1));
            mx = fmaxf(mx, __shfl_xor_sync(0xffffffffu, mx, 2));
            const float mnew = fmaxf(m_i[h], mx);
            const float corr = __expf(m_i[h] - mnew);
            m_i[h] = mnew;
            float rs = 0.0f;
            const int row = qr0 + gp + 8 * h;
#pragma unroll
            for (int nj = 0; nj < 8; nj++) {
                const float p0 = __expf(s[nj][2 * h]     - mnew);
                const float p1 = __expf(s[nj][2 * h + 1] - mnew);
                rs += p0 + p1;
                *(uint2*)&Ps[row * 68 + nj * 8 + 2 * tg] =
                    make_uint2(f2tf(p0), f2tf(p1));
                o[nj][2 * h]     *= corr;
                o[nj][2 * h + 1] *= corr;
            }
            rs += __shfl_xor_sync(0xffffffffu, rs, 1);
            rs += __shfl_xor_sync(0xffffffffu, rs, 2);
            l_i[h] = l_i[h] * corr + rs;
        }
        __syncwarp();   // Ps rows are warp-private; order STS before LDS

        // ---- O += P @ V
#pragma unroll
        for (int ks = 0; ks < 8; ks++) {
            unsigned a[4];
            const int r = qr0 + gp;
            a[0] = Ps[r * 68 + ks * 8 + tg];
            a[1] = Ps[(r + 8) * 68 + ks * 8 + tg];
            a[2] = Ps[r * 68 + ks * 8 + tg + 4];
            a[3] = Ps[(r + 8) * 68 + ks * 8 + tg + 4];
#pragma unroll
            for (int nj = 0; nj < 8; nj++) {
                unsigned b[2];
                const int d = nj * 8 + gp;
                b[0] = Vt[d * 68 + ks * 8 + tg];
                b[1] = Vt[d * 68 + ks * 8 + tg + 4];
                mma_tf32(o[nj], a, b);
            }
        }
    }

    // ---- write ctx in [B,S,D]
    const int b_ = bh >> 4;
    const int hh = bh & 15;
#pragma unroll
    for (int h = 0; h < 2; h++) {
        const float inv = 1.0f / l_i[h];
        const int s = q0 + qr0 + gp + 8 * h;
#pragma unroll
        for (int nj = 0; nj < 8; nj++) {
            const int d = nj * 8 + 2 * tg;
            float2 v;
            v.x = o[nj][2 * h] * inv;
            v.y = o[nj][2 * h + 1] * inv;
            *(float2*)&ctx[(size_t)(b_ * S_ + s) * D_ + (hh << 6) + d] = v;
        }
    }
}

// ---------------------------------------------------------------------------
extern "C" void kernel_launch(void* const* d_in, const int* in_sizes, int n_in,
                              void* d_out, int out_size)
{
    const float* query = (const float*)d_in[0];
    const float* key   = (const float*)d_in[1];
    const float* value = (const float*)d_in[2];
    const float* Wq    = (const float*)d_in[3];
    const float* bq    = (const float*)d_in[4];
    const float* Wk    = (const float*)d_in[5];
    const float* bk    = (const float*)d_in[6];
    const float* Wv    = (const float*)d_in[7];
    const float* bv    = (const float*)d_in[8];
    const float* Wo    = (const float*)d_in[9];
    const float* bo    = (const float*)d_in[10];

    float *Qp, *Kp, *Vp, *Cp;
    cudaGetSymbolAddress((void**)&Qp, g_Q);
    cudaGetSymbolAddress((void**)&Kp, g_K);
    cudaGetSymbolAddress((void**)&Vp, g_V);
    cudaGetSymbolAddress((void**)&Cp, g_ctx);

    cudaFuncSetAttribute(flash_tf32_kernel,
                         cudaFuncAttributeMaxDynamicSharedMemorySize, FL_SMEM);

    const dim3 gg(D_ / 128, M_ / 128);   // (8, 32)
    gemm_tf32_kernel<<<gg, 256>>>(query, Wq, bq, Qp, 1);
    gemm_tf32_kernel<<<gg, 256>>>(key,   Wk, bk, Kp, 1);
    gemm_tf32_kernel<<<gg, 256>>>(value, Wv, bv, Vp, 1);

    flash_tf32_kernel<<<dim3(S_ / 64, B_ * H_), 128, FL_SMEM>>>(Qp, Kp, Vp, Cp);

    gemm_tf32_kernel<<<gg, 256>>>(Cp, Wo, bo, (float*)d_out, 0);
}

// round 3
// speedup vs baseline: 3.2959x; 1.5134x over previous
#include <cuda_runtime.h>

#define D_   1024
#define H_   16
#define HD_  64
#define B_   2
#define S_   2048
#define M_   (B_ * S_)          // 4096

// ---------------- scratch (device globals; no allocation allowed) ----------
__device__ float g_Q[(size_t)M_ * D_];     // [B,H,S,HD]
__device__ float g_K[(size_t)M_ * D_];     // [B,H,S,HD]
__device__ float g_V[(size_t)M_ * D_];     // [B,H,HD,S]  (transposed!)
__device__ float g_ctx[(size_t)M_ * D_];   // [B,S,D]

// ---------------------------------------------------------------------------
// helpers
// ---------------------------------------------------------------------------
__device__ __forceinline__ unsigned f2tf(float f) {
    unsigned u;
    asm("cvt.rna.tf32.f32 %0, %1;" : "=r"(u) : "f"(f));
    return u;
}
__device__ __forceinline__ uint4 tf4(float4 v) {
    return make_uint4(f2tf(v.x), f2tf(v.y), f2tf(v.z), f2tf(v.w));
}
__device__ __forceinline__ float ex2(float x) {
    float y; asm("ex2.approx.ftz.f32 %0, %1;" : "=f"(y) : "f"(x)); return y;
}
__device__ __forceinline__ void mma_tf32(float c[4], const unsigned a[4], const unsigned b[2]) {
    asm volatile(
        "mma.sync.aligned.m16n8k8.row.col.f32.tf32.tf32.f32 "
        "{%0,%1,%2,%3}, {%4,%5,%6,%7}, {%8,%9}, {%0,%1,%2,%3};\n"
        : "+f"(c[0]), "+f"(c[1]), "+f"(c[2]), "+f"(c[3])
        : "r"(a[0]), "r"(a[1]), "r"(a[2]), "r"(a[3]), "r"(b[0]), "r"(b[1]));
}

// ---------------------------------------------------------------------------
// GEMM body (tf32): C[m,e] = A[m,:] . W[e,:] + bias[e]
// BM=BN=128, BK=16, double-buffered smem (1 sync/iter).
// mode 0: out [M,D]; mode 1: out [B,H,S,HD]; mode 2: out [B,H,HD,S] (transposed)
// ---------------------------------------------------------------------------
__device__ __forceinline__ void gemm_body(
    const float* __restrict__ A,
    const float* __restrict__ W,
    const float* __restrict__ bias,
    float* __restrict__ out,
    int mode)
{
    __shared__ __align__(16) unsigned As[2][128 * 20];
    __shared__ __align__(16) unsigned Bs[2][128 * 20];

    const int t    = threadIdx.x;
    const int lane = t & 31;
    const int w    = t >> 5;
    const int wr   = w >> 1;
    const int wc   = w & 1;
    const int gp   = lane >> 2;
    const int tg   = lane & 3;

    const int m0 = blockIdx.y << 7;
    const int n0 = blockIdx.x << 7;

    const int lrow = t >> 1;
    const int lk8  = (t & 1) << 3;
    const float* Ap = A + (size_t)(m0 + lrow) * D_ + lk8;
    const float* Wp = W + (size_t)(n0 + lrow) * D_ + lk8;

    float acc[2][8][4];
#pragma unroll
    for (int mi = 0; mi < 2; mi++)
#pragma unroll
        for (int nj = 0; nj < 8; nj++)
#pragma unroll
            for (int q = 0; q < 4; q++) acc[mi][nj][q] = 0.0f;

    // stage 0
    {
        float4 a0 = *(const float4*)(Ap);
        float4 a1 = *(const float4*)(Ap + 4);
        float4 b0 = *(const float4*)(Wp);
        float4 b1 = *(const float4*)(Wp + 4);
        *(uint4*)&As[0][lrow * 20 + lk8]     = tf4(a0);
        *(uint4*)&As[0][lrow * 20 + lk8 + 4] = tf4(a1);
        *(uint4*)&Bs[0][lrow * 20 + lk8]     = tf4(b0);
        *(uint4*)&Bs[0][lrow * 20 + lk8 + 4] = tf4(b1);
    }
    __syncthreads();

    for (int k0 = 0; k0 < 64; k0++) {
        const int cur = k0 & 1;
        float4 a0, a1, b0, b1;
        if (k0 < 63) {
            const int off = (k0 + 1) * 16;
            a0 = *(const float4*)(Ap + off);
            a1 = *(const float4*)(Ap + off + 4);
            b0 = *(const float4*)(Wp + off);
            b1 = *(const float4*)(Wp + off + 4);
        }

#pragma unroll
        for (int ks = 0; ks < 2; ks++) {
            unsigned a[2][4];
#pragma unroll
            for (int mi = 0; mi < 2; mi++) {
                const int r = wr * 32 + mi * 16 + gp;
                a[mi][0] = As[cur][r * 20 + ks * 8 + tg];
                a[mi][1] = As[cur][(r + 8) * 20 + ks * 8 + tg];
                a[mi][2] = As[cur][r * 20 + ks * 8 + tg + 4];
                a[mi][3] = As[cur][(r + 8) * 20 + ks * 8 + tg + 4];
            }
#pragma unroll
            for (int nj = 0; nj < 8; nj++) {
                unsigned b[2];
                const int n = wc * 64 + nj * 8 + gp;
                b[0] = Bs[cur][n * 20 + ks * 8 + tg];
                b[1] = Bs[cur][n * 20 + ks * 8 + tg + 4];
#pragma unroll
                for (int mi = 0; mi < 2; mi++)
                    mma_tf32(acc[mi][nj], a[mi], b);
            }
        }

        if (k0 < 63) {
            const int nxt = cur ^ 1;
            *(uint4*)&As[nxt][lrow * 20 + lk8]     = tf4(a0);
            *(uint4*)&As[nxt][lrow * 20 + lk8 + 4] = tf4(a1);
            *(uint4*)&Bs[nxt][lrow * 20 + lk8]     = tf4(b0);
            *(uint4*)&Bs[nxt][lrow * 20 + lk8 + 4] = tf4(b1);
            __syncthreads();
        }
    }

    // epilogue
#pragma unroll
    for (int mi = 0; mi < 2; mi++) {
#pragma unroll
        for (int h = 0; h < 2; h++) {
            const int m = m0 + wr * 32 + mi * 16 + gp + h * 8;
            const int b_ = m >> 11;
            const int s  = m & (S_ - 1);
#pragma unroll
            for (int nj = 0; nj < 8; nj++) {
                const int e = n0 + wc * 64 + nj * 8 + 2 * tg;
                float2 v;
                v.x = acc[mi][nj][2 * h]     + bias[e];
                v.y = acc[mi][nj][2 * h + 1] + bias[e + 1];
                if (mode == 0) {
                    *(float2*)&out[(size_t)m * D_ + e] = v;
                } else if (mode == 1) {
                    const int hh = e >> 6, hd = e & 63;
                    *(float2*)&out[(((size_t)(b_ * H_ + hh) * S_ + s) << 6) + hd] = v;
                } else {
                    const int hh = e >> 6, hd = e & 63;
                    float* p = &out[(((size_t)(b_ * H_ + hh) * HD_ + hd)) * S_ + s];
                    p[0]  = v.x;
                    p[S_] = v.y;   // hd+1, same head (e even)
                }
            }
        }
    }
}

__global__ __launch_bounds__(256, 2) void qkv_gemm_kernel(
    const float* __restrict__ Aq, const float* __restrict__ Ak, const float* __restrict__ Av,
    const float* __restrict__ Wq, const float* __restrict__ Wk, const float* __restrict__ Wv,
    const float* __restrict__ bq, const float* __restrict__ bk, const float* __restrict__ bv,
    float* __restrict__ Qo, float* __restrict__ Ko, float* __restrict__ Vo)
{
    const int z = blockIdx.z;
    const float* A = (z == 0) ? Aq : (z == 1) ? Ak : Av;
    const float* W = (z == 0) ? Wq : (z == 1) ? Wk : Wv;
    const float* b = (z == 0) ? bq : (z == 1) ? bk : bv;
    float* o       = (z == 0) ? Qo : (z == 1) ? Ko : Vo;
    gemm_body(A, W, b, o, (z == 2) ? 2 : 1);
}

__global__ __launch_bounds__(256, 2) void out_gemm_kernel(
    const float* __restrict__ A, const float* __restrict__ W,
    const float* __restrict__ bias, float* __restrict__ out)
{
    gemm_body(A, W, bias, out, 0);
}

// ---------------------------------------------------------------------------
// Flash attention, tf32, register-P, Q-in-regs, double-buffered K/V.
// 256 threads (8 warps). Q-tile 128 (16 rows/warp), K-tile 32.
// Q,K: [bh][s][64]; V: [bh][64][s] (pre-transposed by V GEMM).
// k-permutation sigma: frag position j holds logical k = (j<4 ? 2j : 2(j-4)+1),
// applied to ALL mma operands -> S-output frag doubles as PV A-frag, and all
// B/A loads are LDS.64 of adjacent words.
// ---------------------------------------------------------------------------
__global__ __launch_bounds__(256, 2) void flash_tf32_kernel(
    const float* __restrict__ Q,
    const float* __restrict__ K,
    const float* __restrict__ V,
    float* __restrict__ ctx)
{
    __shared__ __align__(16) unsigned Ks[2][32 * 72];
    __shared__ __align__(16) unsigned Vt[2][64 * 40];

    const int t    = threadIdx.x;
    const int lane = t & 31;
    const int w    = t >> 5;
    const int gp   = lane >> 2;
    const int tg   = lane & 3;
    const int qr0  = w << 4;

    const int bh = blockIdx.y;
    const int q0 = blockIdx.x << 7;

    const float* Qb = Q + (size_t)bh * S_ * HD_;
    const float* Kb = K + (size_t)bh * S_ * HD_;
    const float* Vb = V + (size_t)bh * HD_ * S_;

    // tile-load mappings
    const int krow = t >> 4;            // 0..15 (+16)
    const int kf   = (t & 15) << 2;
    const int vd   = t >> 3;            // 0..31 (+32)
    const int vf   = (t & 7) << 2;      // c-chunk 0..28

    const float SC = 0.125f * 1.44269504088896340736f;  // sm_scale * log2(e)

    // ---- Q fragments in registers (permuted: pos tg -> logical 2tg)
    unsigned qa[8][4];
#pragma unroll
    for (int ks = 0; ks < 8; ks++) {
        float2 x0 = *(const float2*)&Qb[(size_t)(q0 + qr0 + gp) * HD_ + ks * 8 + 2 * tg];
        float2 x1 = *(const float2*)&Qb[(size_t)(q0 + qr0 + 8 + gp) * HD_ + ks * 8 + 2 * tg];
        qa[ks][0] = f2tf(x0.x * SC);
        qa[ks][2] = f2tf(x0.y * SC);
        qa[ks][1] = f2tf(x1.x * SC);
        qa[ks][3] = f2tf(x1.y * SC);
    }

    // ---- stage tile 0
    {
        float4 k0v = *(const float4*)&Kb[(size_t)krow * HD_ + kf];
        float4 k1v = *(const float4*)&Kb[(size_t)(krow + 16) * HD_ + kf];
        float4 v0v = *(const float4*)&Vb[(size_t)vd * S_ + vf];
        float4 v1v = *(const float4*)&Vb[(size_t)(vd + 32) * S_ + vf];
        *(uint4*)&Ks[0][krow * 72 + kf]        = tf4(k0v);
        *(uint4*)&Ks[0][(krow + 16) * 72 + kf] = tf4(k1v);
        *(uint4*)&Vt[0][vd * 40 + vf]          = tf4(v0v);
        *(uint4*)&Vt[0][(vd + 32) * 40 + vf]   = tf4(v1v);
    }
    __syncthreads();

    float m_i[2] = {-1e30f, -1e30f};
    float l_i[2] = {0.0f, 0.0f};
    float o[8][4];
#pragma unroll
    for (int dj = 0; dj < 8; dj++)
#pragma unroll
        for (int q = 0; q < 4; q++) o[dj][q] = 0.0f;

    for (int it = 0; it < S_ / 32; it++) {
        const int cur = it & 1;
        const bool pre = (it < S_ / 32 - 1);
        float4 nk0, nk1, nv0, nv1;
        if (pre) {
            const int kn = (it + 1) << 5;
            nk0 = *(const float4*)&Kb[(size_t)(kn + krow) * HD_ + kf];
            nk1 = *(const float4*)&Kb[(size_t)(kn + krow + 16) * HD_ + kf];
            nv0 = *(const float4*)&Vb[(size_t)vd * S_ + kn + vf];
            nv1 = *(const float4*)&Vb[(size_t)(vd + 32) * S_ + kn + vf];
        }

        // ---- S = Q K^T  (32x per warp-row-block: nj 0..3 cover 32 keys)
        float s[4][4];
#pragma unroll
        for (int nj = 0; nj < 4; nj++)
#pragma unroll
            for (int q = 0; q < 4; q++) s[nj][q] = 0.0f;

#pragma unroll
        for (int ks = 0; ks < 8; ks++) {
#pragma unroll
            for (int nj = 0; nj < 4; nj++) {
                uint2 bv_ = *(const uint2*)&Ks[cur][(nj * 8 + gp) * 72 + ks * 8 + 2 * tg];
                unsigned bb[2] = {bv_.x, bv_.y};
                mma_tf32(s[nj], qa[ks], bb);
            }
        }

        // stage next K while S results settle
        if (pre) {
            const int nxt = cur ^ 1;
            *(uint4*)&Ks[nxt][krow * 72 + kf]        = tf4(nk0);
            *(uint4*)&Ks[nxt][(krow + 16) * 72 + kf] = tf4(nk1);
        }

        // ---- online softmax (log2 domain; scores already *log2e via Q scale)
        float pf[4][4];
#pragma unroll
        for (int h = 0; h < 2; h++) {
            float mx = -1e30f;
#pragma unroll
            for (int nj = 0; nj < 4; nj++)
                mx = fmaxf(mx, fmaxf(s[nj][2 * h], s[nj][2 * h + 1]));
            mx = fmaxf(mx, __shfl_xor_sync(0xffffffffu, mx, 1));
            mx = fmaxf(mx, __shfl_xor_sync(0xffffffffu, mx, 2));
            const float mnew = fmaxf(m_i[h], mx);
            const float corr = ex2(m_i[h] - mnew);
            m_i[h] = mnew;
            float rs = 0.0f;
#pragma unroll
            for (int nj = 0; nj < 4; nj++) {
                const float p0 = ex2(s[nj][2 * h] - mnew);
                const float p1 = ex2(s[nj][2 * h + 1] - mnew);
                pf[nj][2 * h]     = p0;
                pf[nj][2 * h + 1] = p1;
                rs += p0 + p1;
            }
            rs += __shfl_xor_sync(0xffffffffu, rs, 1);
            rs += __shfl_xor_sync(0xffffffffu, rs, 2);
            l_i[h] = l_i[h] * corr + rs;
#pragma unroll
            for (int dj = 0; dj < 8; dj++) {
                o[dj][2 * h]     *= corr;
                o[dj][2 * h + 1] *= corr;
            }
        }

        // P frags: S-output frag IS the PV A-frag under sigma: {c0,c2,c1,c3}
        unsigned pa[4][4];
#pragma unroll
        for (int nj = 0; nj < 4; nj++) {
            pa[nj][0] = f2tf(pf[nj][0]);
            pa[nj][1] = f2tf(pf[nj][2]);
            pa[nj][2] = f2tf(pf[nj][1]);
            pa[nj][3] = f2tf(pf[nj][3]);
        }

        // stage next V
        if (pre) {
            const int nxt = cur ^ 1;
            *(uint4*)&Vt[nxt][vd * 40 + vf]        = tf4(nv0);
            *(uint4*)&Vt[nxt][(vd + 32) * 40 + vf] = tf4(nv1);
        }

        // ---- O += P @ V
#pragma unroll
        for (int kb = 0; kb < 4; kb++) {
#pragma unroll
            for (int dj = 0; dj < 8; dj++) {
                uint2 bv_ = *(const uint2*)&Vt[cur][(dj * 8 + gp) * 40 + kb * 8 + 2 * tg];
                unsigned bb[2] = {bv_.x, bv_.y};
                mma_tf32(o[dj], pa[kb], bb);
            }
        }

        __syncthreads();
    }

    // ---- write ctx [B,S,D]
    const int b_ = bh >> 4;
    const int hh = bh & 15;
#pragma unroll
    for (int h = 0; h < 2; h++) {
        const float inv = 1.0f / l_i[h];
        const int srow = q0 + qr0 + gp + 8 * h;
#pragma unroll
        for (int dj = 0; dj < 8; dj++) {
            float2 v;
            v.x = o[dj][2 * h]     * inv;
            v.y = o[dj][2 * h + 1] * inv;
            *(float2*)&ctx[(size_t)(b_ * S_ + srow) * D_ + (hh << 6) + dj * 8 + 2 * tg] = v;
        }
    }
}

// ---------------------------------------------------------------------------
extern "C" void kernel_launch(void* const* d_in, const int* in_sizes, int n_in,
                              void* d_out, int out_size)
{
    const float* query = (const float*)d_in[0];
    const float* key   = (const float*)d_in[1];
    const float* value = (const float*)d_in[2];
    const float* Wq    = (const float*)d_in[3];
    const float* bq    = (const float*)d_in[4];
    const float* Wk    = (const float*)d_in[5];
    const float* bk    = (const float*)d_in[6];
    const float* Wv    = (const float*)d_in[7];
    const float* bv    = (const float*)d_in[8];
    const float* Wo    = (const float*)d_in[9];
    const float* bo    = (const float*)d_in[10];

    float *Qp, *Kp, *Vp, *Cp;
    cudaGetSymbolAddress((void**)&Qp, g_Q);
    cudaGetSymbolAddress((void**)&Kp, g_K);
    cudaGetSymbolAddress((void**)&Vp, g_V);
    cudaGetSymbolAddress((void**)&Cp, g_ctx);

    qkv_gemm_kernel<<<dim3(D_ / 128, M_ / 128, 3), 256>>>(
        query, key, value, Wq, Wk, Wv, bq, bk, bv, Qp, Kp, Vp);

    flash_tf32_kernel<<<dim3(S_ / 128, B_ * H_), 256>>>(Qp, Kp, Vp, Cp);

    out_gemm_kernel<<<dim3(D_ / 128, M_ / 128), 256>>>(Cp, Wo, bo, (float*)d_out);
}

// round 7
// speedup vs baseline: 3.6795x; 1.1164x over previous
#include <cuda_runtime.h>
#include <cuda_fp16.h>
#include <cstdint>

#define D_   1024
#define H_   16
#define HD_  64
#define B_   2
#define S_   2048
#define M_   (B_ * S_)          // 4096
#define RW   24                 // GEMM smem row stride (words); 16 used
#define KW   40                 // flash K smem row stride (words); 32 used
#define VW   24                 // flash V smem row stride (words); 16 used

// ---------------- scratch (device globals; fp16 stored as u32 words) -------
__device__ unsigned g_Qh[(size_t)M_ * D_ / 2];   // [B,H,S,32w] permuted halves
__device__ unsigned g_Kh[(size_t)M_ * D_ / 2];   // [B,H,S,32w] permuted halves
__device__ unsigned g_Vh[(size_t)M_ * D_ / 2];   // [B,H,64,S/2w] perm along s
__device__ unsigned g_Ch[(size_t)M_ * D_ / 2];   // [M,512w] ctx permuted halves

// ---------------------------------------------------------------------------
// helpers
// ---------------------------------------------------------------------------
__device__ __forceinline__ unsigned pack2(float lo, float hi) {
    unsigned r;
    asm("cvt.rn.f16x2.f32 %0, %1, %2;" : "=r"(r) : "f"(hi), "f"(lo));
    return r;
}
__device__ __forceinline__ float ex2(float x) {
    float y; asm("ex2.approx.ftz.f32 %0, %1;" : "=f"(y) : "f"(x)); return y;
}
__device__ __forceinline__ void mma_f16(float c[4], const unsigned a[4], const unsigned b[2]) {
    asm volatile(
        "mma.sync.aligned.m16n8k16.row.col.f32.f16.f16.f32 "
        "{%0,%1,%2,%3}, {%4,%5,%6,%7}, {%8,%9}, {%0,%1,%2,%3};\n"
        : "+f"(c[0]), "+f"(c[1]), "+f"(c[2]), "+f"(c[3])
        : "r"(a[0]), "r"(a[1]), "r"(a[2]), "r"(a[3]), "r"(b[0]), "r"(b[1]));
}

// pack 16 consecutive fp32 into the permuted-half word order (2x uint4):
// word w = 8g+2j holds naturals (16g+2j, +1); word 8g+2j+1 holds (16g+2j+8, +9)
__device__ __forceinline__ void pack16(const float f[16], uint4& lo4, uint4& hi4) {
    lo4 = make_uint4(pack2(f[0], f[1]), pack2(f[8],  f[9]),
                     pack2(f[2], f[3]), pack2(f[10], f[11]));
    hi4 = make_uint4(pack2(f[4], f[5]), pack2(f[12], f[13]),
                     pack2(f[6], f[7]), pack2(f[14], f[15]));
}

// ---------------------------------------------------------------------------
// fp16 GEMM: C[m,e] = A[m,:] . W[e,:] + bias[e]
// BM=BN=128, BK=32 halves, double-buffered.
// smem contract: smem[row*RW + w] = permuted word (w ^ key(row)),
// key(row) = ((row>>2)&1)<<3  -> conflict-free LDS.64 fragment reads.
// modes: 0 float out [M,D]; 1 Q permuted words (scaled); 2 K permuted words;
//        3 V half [B,H,64,S] with per-32 s-permutation
// ---------------------------------------------------------------------------
#define SC_Q 0.18033688011112042f   /* 0.125 * log2(e) */

__device__ __forceinline__ void gemm_fp16_body(
    const float* __restrict__ Af,
    const unsigned* __restrict__ Ah,
    const float* __restrict__ W,
    const float* __restrict__ bias,
    void* __restrict__ outp,
    int mode, int a_is_half)
{
    __shared__ __align__(16) unsigned As[2][128 * RW];
    __shared__ __align__(16) unsigned Bs[2][128 * RW];

    const int t    = threadIdx.x;
    const int lane = t & 31;
    const int w    = t >> 5;
    const int wr   = w >> 1;
    const int wc   = w & 1;
    const int gp   = lane >> 2;
    const int tg   = lane & 3;

    const int m0 = blockIdx.y << 7;
    const int n0 = blockIdx.x << 7;

    const int row  = t & 127;
    const int seg  = t >> 7;
    const int skey = ((row >> 2) & 1) << 3;
    const int wb   = row * RW + ((8 * seg) ^ skey);   // uint4-aligned

    const float*    Ap  = a_is_half ? nullptr : Af + (size_t)(m0 + row) * D_ + seg * 16;
    const unsigned* Ahp = a_is_half ? Ah + (size_t)(m0 + row) * (D_ / 2) + seg * 8 : nullptr;
    const float*    Wp  = W + (size_t)(n0 + row) * D_ + seg * 16;

    float acc[2][8][4];
#pragma unroll
    for (int mi = 0; mi < 2; mi++)
#pragma unroll
        for (int nj = 0; nj < 8; nj++)
#pragma unroll
            for (int q = 0; q < 4; q++) acc[mi][nj][q] = 0.0f;

    // ---- stage chunk 0
    {
        float bf[16];
#pragma unroll
        for (int q = 0; q < 4; q++) {
            float4 v = *(const float4*)(Wp + 4 * q);
            bf[4*q] = v.x; bf[4*q+1] = v.y; bf[4*q+2] = v.z; bf[4*q+3] = v.w;
        }
        uint4 l4, h4; pack16(bf, l4, h4);
        *(uint4*)&Bs[0][wb]     = l4;
        *(uint4*)&Bs[0][wb + 4] = h4;
        if (a_is_half) {
            *(uint4*)&As[0][wb]     = *(const uint4*)(Ahp);
            *(uint4*)&As[0][wb + 4] = *(const uint4*)(Ahp + 4);
        } else {
            float af[16];
#pragma unroll
            for (int q = 0; q < 4; q++) {
                float4 v = *(const float4*)(Ap + 4 * q);
                af[4*q] = v.x; af[4*q+1] = v.y; af[4*q+2] = v.z; af[4*q+3] = v.w;
            }
            uint4 al, ah; pack16(af, al, ah);
            *(uint4*)&As[0][wb]     = al;
            *(uint4*)&As[0][wb + 4] = ah;
        }
    }
    __syncthreads();

    const int fkey = ((gp >> 2) & 1) << 3;   // frag-read key (rows r and r+8 share it)

    for (int kc = 0; kc < D_ / 32; kc++) {
        const int cur = kc & 1;
        const bool pre = (kc < D_ / 32 - 1);

        float bf[16], af[16];
        uint4 ph0, ph1;
        if (pre) {
            const int off = (kc + 1) * 32;
#pragma unroll
            for (int q = 0; q < 4; q++) {
                float4 v = *(const float4*)(Wp + off + 4 * q);
                bf[4*q] = v.x; bf[4*q+1] = v.y; bf[4*q+2] = v.z; bf[4*q+3] = v.w;
            }
            if (a_is_half) {
                ph0 = *(const uint4*)(Ahp + (kc + 1) * 16);
                ph1 = *(const uint4*)(Ahp + (kc + 1) * 16 + 4);
            } else {
#pragma unroll
                for (int q = 0; q < 4; q++) {
                    float4 v = *(const float4*)(Ap + off + 4 * q);
                    af[4*q] = v.x; af[4*q+1] = v.y; af[4*q+2] = v.z; af[4*q+3] = v.w;
                }
            }
        }

        // ---- mma on current buffer
#pragma unroll
        for (int s = 0; s < 2; s++) {
            unsigned a[2][4];
#pragma unroll
            for (int mi = 0; mi < 2; mi++) {
                const int r = wr * 32 + mi * 16 + gp;
                uint2 lo = *(const uint2*)&As[cur][r * RW + ((8 * s + 2 * tg) ^ fkey)];
                uint2 hi = *(const uint2*)&As[cur][(r + 8) * RW + ((8 * s + 2 * tg) ^ fkey)];
                a[mi][0] = lo.x; a[mi][1] = hi.x; a[mi][2] = lo.y; a[mi][3] = hi.y;
            }
#pragma unroll
            for (int nj = 0; nj < 8; nj++) {
                const int nb = wc * 64 + nj * 8 + gp;
                uint2 bb = *(const uint2*)&Bs[cur][nb * RW + ((8 * s + 2 * tg) ^ fkey)];
                unsigned br[2] = {bb.x, bb.y};
                mma_f16(acc[0][nj], a[0], br);
                mma_f16(acc[1][nj], a[1], br);
            }
        }

        // ---- stage next
        if (pre) {
            const int nxt = cur ^ 1;
            uint4 l4, h4; pack16(bf, l4, h4);
            *(uint4*)&Bs[nxt][wb]     = l4;
            *(uint4*)&Bs[nxt][wb + 4] = h4;
            if (a_is_half) {
                *(uint4*)&As[nxt][wb]     = ph0;
                *(uint4*)&As[nxt][wb + 4] = ph1;
            } else {
                uint4 al, ah; pack16(af, al, ah);
                *(uint4*)&As[nxt][wb]     = al;
                *(uint4*)&As[nxt][wb + 4] = ah;
            }
            __syncthreads();
        }
    }

    // ---- epilogue
#pragma unroll
    for (int mi = 0; mi < 2; mi++) {
#pragma unroll
        for (int h = 0; h < 2; h++) {
            const int m  = m0 + wr * 32 + mi * 16 + gp + h * 8;
            const int b_ = m >> 11;
            const int s  = m & (S_ - 1);
#pragma unroll
            for (int nj = 0; nj < 8; nj++) {
                const int e  = n0 + wc * 64 + nj * 8 + 2 * tg;
                const float vx = acc[mi][nj][2 * h]     + bias[e];
                const float vy = acc[mi][nj][2 * h + 1] + bias[e + 1];
                if (mode == 0) {
                    *(float2*)((float*)outp + (size_t)m * D_ + e) = make_float2(vx, vy);
                } else if (mode == 1 || mode == 2) {
                    const int hh = e >> 6, hd = e & 63;
                    const float sc = (mode == 1) ? SC_Q : 1.0f;
                    const int wpos = 8 * (hd >> 4) + 2 * ((hd >> 1) & 3) + ((hd >> 3) & 1);
                    ((unsigned*)outp)[(((size_t)(b_ * H_ + hh) * S_ + s) << 5) + wpos] =
                        pack2(vx * sc, vy * sc);
                } else {
                    const int hh = e >> 6, hd = e & 63;
                    const int y  = s & 31;
                    const int sp = 32 * (s >> 5) + 16 * (y >> 4) + 4 * ((y >> 1) & 3)
                                 + 2 * ((y >> 3) & 1) + (y & 1);
                    __half* vo = (__half*)outp + (((size_t)(b_ * H_ + hh) * HD_ + hd)) * S_;
                    vo[sp]      = __float2half_rn(vx);
                    vo[S_ + sp] = __float2half_rn(vy);
                }
            }
        }
    }
}

__global__ __launch_bounds__(256, 2) void qkv_gemm_kernel(
    const float* __restrict__ Aq, const float* __restrict__ Ak, const float* __restrict__ Av,
    const float* __restrict__ Wq, const float* __restrict__ Wk, const float* __restrict__ Wv,
    const float* __restrict__ bq, const float* __restrict__ bk, const float* __restrict__ bv,
    unsigned* __restrict__ Qo, unsigned* __restrict__ Ko, unsigned* __restrict__ Vo)
{
    const int z = blockIdx.z;
    const float* A = (z == 0) ? Aq : (z == 1) ? Ak : Av;
    const float* W = (z == 0) ? Wq : (z == 1) ? Wk : Wv;
    const float* b = (z == 0) ? bq : (z == 1) ? bk : bv;
    void* o        = (z == 0) ? (void*)Qo : (z == 1) ? (void*)Ko : (void*)Vo;
    gemm_fp16_body(A, nullptr, W, b, o, (z == 0) ? 1 : (z == 1) ? 2 : 3, 0);
}

__global__ __launch_bounds__(256, 2) void out_gemm_kernel(
    const unsigned* __restrict__ Ah, const float* __restrict__ W,
    const float* __restrict__ bias, float* __restrict__ out)
{
    gemm_fp16_body(nullptr, Ah, W, bias, (void*)out, 0, 1);
}

// ---------------------------------------------------------------------------
// Flash attention, fp16 m16n8k16. 256 threads, Q-tile 128 rows (16/warp),
// K-tile 32 keys, double-buffered K/V smem, Q + P in registers.
// K smem: 32 rows x 32 words, stride KW=40 (conflict-free, no swizzle).
// V smem: 64 rows x 16 words, stride VW=24 (conflict-free, no swizzle).
// ---------------------------------------------------------------------------
__global__ __launch_bounds__(256, 2) void flash_fp16_kernel(
    const unsigned* __restrict__ Q,
    const unsigned* __restrict__ K,
    const unsigned* __restrict__ V,
    unsigned* __restrict__ ctx)
{
    __shared__ __align__(16) unsigned Ks[2][32 * KW];
    __shared__ __align__(16) unsigned Vt[2][64 * VW];

    const int t    = threadIdx.x;
    const int lane = t & 31;
    const int w    = t >> 5;
    const int gp   = lane >> 2;
    const int tg   = lane & 3;
    const int qr0  = w << 4;

    const int bh = blockIdx.y;
    const int q0 = blockIdx.x << 7;

    const unsigned* Qw = Q + (size_t)bh * S_ * 32;
    const unsigned* Kw = K + (size_t)bh * S_ * 32;
    const unsigned* Vw = V + (size_t)bh * HD_ * (S_ / 2);

    // loader mappings (conflict-free STS.128)
    const int krow = (t & 3) + 4 * (t >> 5);    // 0..31
    const int kj   = (t >> 2) & 7;              // word quad 0..7
    const int vrow = (t & 3) + 4 * (t >> 4);    // 0..63
    const int vj   = (t >> 2) & 3;              // word quad 0..3

    // ---- Q fragments in registers
    unsigned qa[4][4];
#pragma unroll
    for (int s = 0; s < 4; s++) {
        uint2 lo = *(const uint2*)&Qw[(size_t)(q0 + qr0 + gp) * 32 + 8 * s + 2 * tg];
        uint2 hi = *(const uint2*)&Qw[(size_t)(q0 + qr0 + 8 + gp) * 32 + 8 * s + 2 * tg];
        qa[s][0] = lo.x; qa[s][1] = hi.x; qa[s][2] = lo.y; qa[s][3] = hi.y;
    }

    // ---- stage tile 0
    *(uint4*)&Ks[0][krow * KW + 4 * kj] = *(const uint4*)&Kw[(size_t)krow * 32 + 4 * kj];
    *(uint4*)&Vt[0][vrow * VW + 4 * vj] = *(const uint4*)&Vw[(size_t)vrow * (S_ / 2) + 4 * vj];
    __syncthreads();

    float m_i[2] = {-1e30f, -1e30f};
    float l_i[2] = {0.0f, 0.0f};
    float o[8][4];
#pragma unroll
    for (int dj = 0; dj < 8; dj++)
#pragma unroll
        for (int q = 0; q < 4; q++) o[dj][q] = 0.0f;

    for (int it = 0; it < S_ / 32; it++) {
        const int cur = it & 1;
        const bool pre = (it < S_ / 32 - 1);
        uint4 nk, nv;
        if (pre) {
            const int kn = (it + 1) << 5;
            nk = *(const uint4*)&Kw[(size_t)(kn + krow) * 32 + 4 * kj];
            nv = *(const uint4*)&Vw[(size_t)vrow * (S_ / 2) + kn / 2 + 4 * vj];
        }

        // ---- S = Q K^T
        float s[4][4];
#pragma unroll
        for (int nj = 0; nj < 4; nj++)
#pragma unroll
            for (int q = 0; q < 4; q++) s[nj][q] = 0.0f;

#pragma unroll
        for (int ks = 0; ks < 4; ks++) {
#pragma unroll
            for (int nj = 0; nj < 4; nj++) {
                const int c = nj * 8 + gp;
                uint2 bb = *(const uint2*)&Ks[cur][c * KW + 8 * ks + 2 * tg];
                unsigned br[2] = {bb.x, bb.y};
                mma_f16(s[nj], qa[ks], br);
            }
        }

        if (pre)
            *(uint4*)&Ks[cur ^ 1][krow * KW + 4 * kj] = nk;

        // ---- online softmax (exp2 domain; Q pre-scaled)
#pragma unroll
        for (int h = 0; h < 2; h++) {
            float mx = -1e30f;
#pragma unroll
            for (int nj = 0; nj < 4; nj++)
                mx = fmaxf(mx, fmaxf(s[nj][2 * h], s[nj][2 * h + 1]));
            mx = fmaxf(mx, __shfl_xor_sync(0xffffffffu, mx, 1));
            mx = fmaxf(mx, __shfl_xor_sync(0xffffffffu, mx, 2));
            const float mnew = fmaxf(m_i[h], mx);
            const float corr = ex2(m_i[h] - mnew);
            m_i[h] = mnew;
            float rs = 0.0f;
#pragma unroll
            for (int nj = 0; nj < 4; nj++) {
                s[nj][2 * h]     = ex2(s[nj][2 * h] - mnew);
                s[nj][2 * h + 1] = ex2(s[nj][2 * h + 1] - mnew);
                rs += s[nj][2 * h] + s[nj][2 * h + 1];
            }
            rs += __shfl_xor_sync(0xffffffffu, rs, 1);
            rs += __shfl_xor_sync(0xffffffffu, rs, 2);
            l_i[h] = l_i[h] * corr + rs;
#pragma unroll
            for (int dj = 0; dj < 8; dj++) {
                o[dj][2 * h]     *= corr;
                o[dj][2 * h + 1] *= corr;
            }
        }

        // ---- P fragments
        unsigned pa[2][4];
#pragma unroll
        for (int cp = 0; cp < 2; cp++) {
            pa[cp][0] = pack2(s[2 * cp][0],     s[2 * cp][1]);
            pa[cp][1] = pack2(s[2 * cp][2],     s[2 * cp][3]);
            pa[cp][2] = pack2(s[2 * cp + 1][0], s[2 * cp + 1][1]);
            pa[cp][3] = pack2(s[2 * cp + 1][2], s[2 * cp + 1][3]);
        }

        if (pre)
            *(uint4*)&Vt[cur ^ 1][vrow * VW + 4 * vj] = nv;

        // ---- O += P @ V
#pragma unroll
        for (int cp = 0; cp < 2; cp++) {
#pragma unroll
            for (int dj = 0; dj < 8; dj++) {
                const int d = dj * 8 + gp;
                uint2 bb = *(const uint2*)&Vt[cur][d * VW + 8 * cp + 2 * tg];
                unsigned br[2] = {bb.x, bb.y};
                mma_f16(o[dj], pa[cp], br);
            }
        }

        __syncthreads();
    }

    // ---- write ctx: permuted fp16 words [M][512w]
    const int b_ = bh >> 4;
    const int hh = bh & 15;
#pragma unroll
    for (int h = 0; h < 2; h++) {
        const float inv = 1.0f / l_i[h];
        const int srow = q0 + qr0 + gp + 8 * h;
        unsigned* co = ctx + ((size_t)(b_ * S_ + srow) << 9) + (hh << 5);
#pragma unroll
        for (int dj = 0; dj < 8; dj++) {
            const int wpos = 8 * (dj >> 1) + 2 * tg + (dj & 1);
            co[wpos] = pack2(o[dj][2 * h] * inv, o[dj][2 * h + 1] * inv);
        }
    }
}

// ---------------------------------------------------------------------------
extern "C" void kernel_launch(void* const* d_in, const int* in_sizes, int n_in,
                              void* d_out, int out_size)
{
    const float* query = (const float*)d_in[0];
    const float* key   = (const float*)d_in[1];
    const float* value = (const float*)d_in[2];
    const float* Wq    = (const float*)d_in[3];
    const float* bq    = (const float*)d_in[4];
    const float* Wk    = (const float*)d_in[5];
    const float* bk    = (const float*)d_in[6];
    const float* Wv    = (const float*)d_in[7];
    const float* bv    = (const float*)d_in[8];
    const float* Wo    = (const float*)d_in[9];
    const float* bo    = (const float*)d_in[10];

    unsigned *Qp, *Kp, *Vp, *Cp;
    cudaGetSymbolAddress((void**)&Qp, g_Qh);
    cudaGetSymbolAddress((void**)&Kp, g_Kh);
    cudaGetSymbolAddress((void**)&Vp, g_Vh);
    cudaGetSymbolAddress((void**)&Cp, g_Ch);

    qkv_gemm_kernel<<<dim3(D_ / 128, M_ / 128, 3), 256>>>(
        query, key, value, Wq, Wk, Wv, bq, bk, bv, Qp, Kp, Vp);

    flash_fp16_kernel<<<dim3(S_ / 128, B_ * H_), 256>>>(Qp, Kp, Vp, Cp);

    out_gemm_kernel<<<dim3(D_ / 128, M_ / 128), 256>>>(Cp, Wo, bo, (float*)d_out);
}

// round 8
// speedup vs baseline: 7.7194x; 2.0980x over previous
#include <cuda_runtime.h>
#include <cuda_fp16.h>
#include <cstdint>

#define D_   1024
#define H_   16
#define HD_  64
#define B_   2
#define S_   2048
#define M_   (B_ * S_)          // 4096

// ---------------- scratch (device globals) ---------------------------------
__device__ unsigned g_q16[(size_t)M_ * D_ / 2];     // fp16 natural inputs
__device__ unsigned g_k16[(size_t)M_ * D_ / 2];
__device__ unsigned g_v16[(size_t)M_ * D_ / 2];
__device__ unsigned g_w16[4][(size_t)D_ * D_ / 2];  // Wq,Wk,Wv,Wo fp16
__device__ unsigned g_Qh[(size_t)M_ * D_ / 2];      // [B,H,S,32w] natural, *SC
__device__ unsigned g_Kh[(size_t)M_ * D_ / 2];      // [B,H,S,32w] natural
__device__ unsigned g_Vh[(size_t)M_ * D_ / 2];      // [B,H,64,S] natural (transposed)
__device__ unsigned g_Ch[(size_t)M_ * D_ / 2];      // ctx [M,512w] natural

#define SC_Q 0.18033688011112042f   /* 0.125 * log2(e) */

// ---------------------------------------------------------------------------
// helpers
// ---------------------------------------------------------------------------
__device__ __forceinline__ unsigned pack2(float lo, float hi) {
    unsigned r;
    asm("cvt.rn.f16x2.f32 %0, %1, %2;" : "=r"(r) : "f"(hi), "f"(lo));
    return r;
}
__device__ __forceinline__ float ex2(float x) {
    float y; asm("ex2.approx.ftz.f32 %0, %1;" : "=f"(y) : "f"(x)); return y;
}
__device__ __forceinline__ void mma_f16(float c[4], const unsigned a[4], unsigned b0, unsigned b1) {
    asm volatile(
        "mma.sync.aligned.m16n8k16.row.col.f32.f16.f16.f32 "
        "{%0,%1,%2,%3}, {%4,%5,%6,%7}, {%8,%9}, {%0,%1,%2,%3};\n"
        : "+f"(c[0]), "+f"(c[1]), "+f"(c[2]), "+f"(c[3])
        : "r"(a[0]), "r"(a[1]), "r"(a[2]), "r"(a[3]), "r"(b0), "r"(b1));
}
__device__ __forceinline__ void ldsm4(unsigned& r0, unsigned& r1, unsigned& r2, unsigned& r3,
                                      unsigned addr) {
    asm volatile("ldmatrix.sync.aligned.m8n8.x4.shared.b16 {%0,%1,%2,%3}, [%4];"
                 : "=r"(r0), "=r"(r1), "=r"(r2), "=r"(r3) : "r"(addr));
}
#define CP16(dst, src) \
    asm volatile("cp.async.cg.shared.global [%0], [%1], 16;" :: "r"(dst), "l"(src) : "memory")
#define CP_COMMIT() asm volatile("cp.async.commit_group;" ::: "memory")
#define CP_WAIT1()  asm volatile("cp.async.wait_group 1;" ::: "memory")
#define CP_WAIT0()  asm volatile("cp.async.wait_group 0;" ::: "memory")

// ---------------------------------------------------------------------------
// convert: fp32 -> fp16 natural (q,k,v + 4 weights)
// ---------------------------------------------------------------------------
__global__ __launch_bounds__(256) void convert_kernel(
    const float* __restrict__ q, const float* __restrict__ k, const float* __restrict__ v,
    const float* __restrict__ wq, const float* __restrict__ wk,
    const float* __restrict__ wv, const float* __restrict__ wo)
{
    const int z = blockIdx.z;
    const float* src;
    unsigned* dst;
    size_t n;
    switch (z) {
        case 0: src = q;  dst = g_q16;    n = (size_t)M_ * D_; break;
        case 1: src = k;  dst = g_k16;    n = (size_t)M_ * D_; break;
        case 2: src = v;  dst = g_v16;    n = (size_t)M_ * D_; break;
        case 3: src = wq; dst = g_w16[0]; n = (size_t)D_ * D_; break;
        case 4: src = wk; dst = g_w16[1]; n = (size_t)D_ * D_; break;
        case 5: src = wv; dst = g_w16[2]; n = (size_t)D_ * D_; break;
        default: src = wo; dst = g_w16[3]; n = (size_t)D_ * D_; break;
    }
    const size_t i8 = ((size_t)blockIdx.x * blockDim.x + threadIdx.x) * 8;
    if (i8 >= n) return;
    float4 f0 = *(const float4*)(src + i8);
    float4 f1 = *(const float4*)(src + i8 + 4);
    uint4 o = make_uint4(pack2(f0.x, f0.y), pack2(f0.z, f0.w),
                         pack2(f1.x, f1.y), pack2(f1.z, f1.w));
    *(uint4*)(dst + i8 / 2) = o;
}

// ---------------------------------------------------------------------------
// fp16 GEMM: C[m,e] = A[m,:] . W[e,:] + bias[e]
// CTA 128x128, 128 threads (4 warps, 2x2, warp tile 64x64), BK=64 halves,
// 3-stage cp.async, SW128 smem, ldmatrix fragments.
// modes: 0 float out [M,D]; 1 Q natural words *SC; 2 K natural; 3 V transposed
// ---------------------------------------------------------------------------
#define GSTG   3
#define TILEB  16384   // 128 rows x 128 B per matrix stage
#define GM_SMEM (GSTG * 2 * TILEB)   // 98304

__device__ __forceinline__ void gemm16_body(
    const unsigned* __restrict__ Aw,   // fp16 words [*, 512]
    const unsigned* __restrict__ Ww,   // fp16 words [1024, 512]
    const float* __restrict__ bias,
    void* __restrict__ outp,
    int mode)
{
    extern __shared__ char smc[];
    const unsigned smA = (unsigned)__cvta_generic_to_shared(smc);
    const unsigned smB = smA + GSTG * TILEB;

    const int t    = threadIdx.x;
    const int lane = t & 31;
    const int w    = t >> 5;
    const int gp   = lane >> 2;
    const int tg   = lane & 3;
    const int wm0  = (w >> 1) << 6;
    const int wn0  = (w & 1) << 6;

    const int m0 = blockIdx.y << 7;
    const int n0 = blockIdx.x << 7;

    const unsigned* Ab = Aw + (size_t)m0 * 512;
    const unsigned* Bb = Ww + (size_t)n0 * 512;

    // loader mapping: 8 chunks each of A and B per thread per stage
    const int lr = t >> 3;     // 0..15
    const int lc = t & 7;

    // ldmatrix lane constants
    const int la15 = lane & 15;
    const int ahi  = (lane >> 4) << 4;            // 16*(l>>4)
    const int bsel = ((lane >> 3) & 1) << 4;      // 16*((l>>3)&1)
    const int brow0 = wn0 + ((lane >> 4) << 3) + (lane & 7);

    int arow[4], akey[4];
#pragma unroll
    for (int mi = 0; mi < 4; mi++) {
        const int r = wm0 + 16 * mi + la15;
        arow[mi] = 128 * r;
        akey[mi] = (r & 7) << 4;
    }

    float acc[4][8][4];
#pragma unroll
    for (int mi = 0; mi < 4; mi++)
#pragma unroll
        for (int nj = 0; nj < 8; nj++)
#pragma unroll
            for (int q = 0; q < 4; q++) acc[mi][nj][q] = 0.0f;

    // issue one stage of cp.async
#define GISSUE(st, kc) do {                                                    \
    const unsigned da = smA + (st) * TILEB;                                    \
    const unsigned db = smB + (st) * TILEB;                                    \
    _Pragma("unroll")                                                          \
    for (int i = 0; i < 8; i++) {                                              \
        const int row = lr + 16 * i;                                           \
        const unsigned off = 128u * row + ((16u * lc) ^ ((row & 7) << 4));     \
        CP16(da + off, Ab + (size_t)row * 512 + (kc) * 32 + 4 * lc);           \
        CP16(db + off, Bb + (size_t)row * 512 + (kc) * 32 + 4 * lc);           \
    }                                                                          \
    CP_COMMIT();                                                               \
} while (0)

    GISSUE(0, 0);
    GISSUE(1, 1);

    for (int kc = 0; kc < 16; kc++) {
        if (kc == 15) { CP_WAIT0(); } else { CP_WAIT1(); }
        __syncthreads();
        if (kc + 2 < 16) {
            const int st = (kc + 2) % 3;
            GISSUE(st, kc + 2);
        }

        const unsigned ab = smA + (kc % 3) * TILEB;
        const unsigned bb = smB + (kc % 3) * TILEB;

#pragma unroll
        for (int s = 0; s < 4; s++) {
            unsigned a[4][4];
#pragma unroll
            for (int mi = 0; mi < 4; mi++) {
                const unsigned addr = ab + arow[mi] + ((32 * s + ahi) ^ akey[mi]);
                ldsm4(a[mi][0], a[mi][1], a[mi][2], a[mi][3], addr);
            }
#pragma unroll
            for (int nj2 = 0; nj2 < 4; nj2++) {
                const int row = brow0 + 16 * nj2;
                const unsigned addr = bb + 128u * row + ((32 * s + bsel) ^ ((row & 7) << 4));
                unsigned b0, b1, b2, b3;
                ldsm4(b0, b1, b2, b3, addr);
#pragma unroll
                for (int mi = 0; mi < 4; mi++) {
                    mma_f16(acc[mi][2 * nj2],     a[mi], b0, b1);
                    mma_f16(acc[mi][2 * nj2 + 1], a[mi], b2, b3);
                }
            }
        }
    }
#undef GISSUE

    // ---- epilogue
#pragma unroll
    for (int mi = 0; mi < 4; mi++) {
#pragma unroll
        for (int h = 0; h < 2; h++) {
            const int m  = m0 + wm0 + 16 * mi + gp + 8 * h;
            const int b_ = m >> 11;
            const int s  = m & (S_ - 1);
#pragma unroll
            for (int nj = 0; nj < 8; nj++) {
                const int e  = n0 + wn0 + 8 * nj + 2 * tg;
                const float vx = acc[mi][nj][2 * h]     + bias[e];
                const float vy = acc[mi][nj][2 * h + 1] + bias[e + 1];
                if (mode == 0) {
                    *(float2*)((float*)outp + (size_t)m * D_ + e) = make_float2(vx, vy);
                } else if (mode == 1 || mode == 2) {
                    const int hh = e >> 6, hd = e & 63;
                    const float sc = (mode == 1) ? SC_Q : 1.0f;
                    ((unsigned*)outp)[(((size_t)(b_ * H_ + hh) * S_ + s) << 5) + (hd >> 1)] =
                        pack2(vx * sc, vy * sc);
                } else {
                    const int hh = e >> 6, hd = e & 63;
                    __half* vo = (__half*)outp + (((size_t)(b_ * H_ + hh) * HD_ + hd)) * S_ + s;
                    vo[0]  = __float2half_rn(vx);
                    vo[S_] = __float2half_rn(vy);
                }
            }
        }
    }
}

__global__ __launch_bounds__(128, 2) void qkv_gemm_kernel(
    const float* __restrict__ bq, const float* __restrict__ bk, const float* __restrict__ bv)
{
    const int z = blockIdx.z;
    const unsigned* A = (z == 0) ? g_q16 : (z == 1) ? g_k16 : g_v16;
    const float* b    = (z == 0) ? bq : (z == 1) ? bk : bv;
    void* o           = (z == 0) ? (void*)g_Qh : (z == 1) ? (void*)g_Kh : (void*)g_Vh;
    gemm16_body(A, g_w16[z], b, o, z + 1);
}

__global__ __launch_bounds__(128, 2) void out_gemm_kernel(
    const float* __restrict__ bo, float* __restrict__ out)
{
    gemm16_body(g_Ch, g_w16[3], bo, (void*)out, 0);
}

// ---------------------------------------------------------------------------
// Flash attention fp16. 256 threads (8 warps), Q-tile 128 (16 rows/warp),
// K-tile 32, 3-stage cp.async for K/V, ldmatrix K frags, LDS.32 V frags.
// K smem: SW128 32x32w; V smem: 64 rows x 16w, stride 20.
// ---------------------------------------------------------------------------
#define FSTG 3
#define KSTG_W (32 * 32)     // 1024 words per K stage
#define VSTG_W (64 * 20)     // 1280 words per V stage

__global__ __launch_bounds__(256, 2) void flash_fp16_kernel(float* dummy)
{
    __shared__ __align__(16) unsigned sK[FSTG][KSTG_W];
    __shared__ __align__(16) unsigned sV[FSTG][VSTG_W];

    const unsigned smK = (unsigned)__cvta_generic_to_shared(sK);
    const unsigned smV = (unsigned)__cvta_generic_to_shared(sV);

    const int t    = threadIdx.x;
    const int lane = t & 31;
    const int w    = t >> 5;
    const int gp   = lane >> 2;
    const int tg   = lane & 3;
    const int qr0  = w << 4;

    const int bh = blockIdx.y;
    const int q0 = blockIdx.x << 7;

    const unsigned* Qw = g_Qh + (size_t)bh * S_ * 32;
    const unsigned* Kw = g_Kh + (size_t)bh * S_ * 32;
    const unsigned* Vw = g_Vh + (size_t)bh * HD_ * (S_ / 2);

    // loader mappings
    const int krow = t >> 3;          // 0..31
    const int kj   = t & 7;
    const int vrow = t & 63;          // 0..63
    const int vj   = t >> 6;          // 0..3
    const unsigned kdst_off = 128u * krow + ((16u * kj) ^ ((krow & 7) << 4));
    const unsigned vdst_off = (vrow * 20 + 4 * vj) * 4;

#define FISSUE(st, it) do {                                                    \
    const int kn = (it) << 5;                                                  \
    CP16(smK + (st) * 4096 + kdst_off, Kw + (size_t)(kn + krow) * 32 + 4 * kj);\
    CP16(smV + (st) * 5120 + vdst_off,                                         \
         Vw + (size_t)vrow * (S_ / 2) + (kn >> 1) + 4 * vj);                   \
    CP_COMMIT();                                                               \
} while (0)

    // ---- Q fragments (natural layout, pre-scaled)
    unsigned qa[4][4];
#pragma unroll
    for (int s = 0; s < 4; s++) {
        const unsigned* r0 = Qw + (size_t)(q0 + qr0 + gp) * 32;
        const unsigned* r1 = Qw + (size_t)(q0 + qr0 + 8 + gp) * 32;
        qa[s][0] = r0[8 * s + tg];
        qa[s][1] = r1[8 * s + tg];
        qa[s][2] = r0[8 * s + tg + 4];
        qa[s][3] = r1[8 * s + tg + 4];
    }

    FISSUE(0, 0);
    FISSUE(1, 1);

    // ldmatrix K lane constants
    const int kbrow0 = ((lane >> 4) << 3) + (lane & 7);
    const int kbsel  = ((lane >> 3) & 1) << 4;

    float m_i[2] = {-1e30f, -1e30f};
    float l_i[2] = {0.0f, 0.0f};
    float o[8][4];
#pragma unroll
    for (int dj = 0; dj < 8; dj++)
#pragma unroll
        for (int q = 0; q < 4; q++) o[dj][q] = 0.0f;

    for (int it = 0; it < 64; it++) {
        if (it == 63) { CP_WAIT0(); } else { CP_WAIT1(); }
        __syncthreads();
        if (it + 2 < 64) {
            const int st = (it + 2) % 3;
            FISSUE(st, it + 2);
        }

        const int cs = it % 3;
        const unsigned kb = smK + cs * 4096;
        const unsigned* vb = &sV[cs][0];

        // ---- S = Q K^T
        float s[4][4];
#pragma unroll
        for (int nj = 0; nj < 4; nj++)
#pragma unroll
            for (int q = 0; q < 4; q++) s[nj][q] = 0.0f;

#pragma unroll
        for (int ks = 0; ks < 4; ks++) {
#pragma unroll
            for (int nj2 = 0; nj2 < 2; nj2++) {
                const int row = 16 * nj2 + kbrow0;
                const unsigned addr = kb + 128u * row + ((32 * ks + kbsel) ^ ((row & 7) << 4));
                unsigned b0, b1, b2, b3;
                ldsm4(b0, b1, b2, b3, addr);
                mma_f16(s[2 * nj2],     qa[ks], b0, b1);
                mma_f16(s[2 * nj2 + 1], qa[ks], b2, b3);
            }
        }

        // ---- online softmax (exp2 domain)
#pragma unroll
        for (int h = 0; h < 2; h++) {
            float mx = -1e30f;
#pragma unroll
            for (int nj = 0; nj < 4; nj++)
                mx = fmaxf(mx, fmaxf(s[nj][2 * h], s[nj][2 * h + 1]));
            mx = fmaxf(mx, __shfl_xor_sync(0xffffffffu, mx, 1));
            mx = fmaxf(mx, __shfl_xor_sync(0xffffffffu, mx, 2));
            const float mnew = fmaxf(m_i[h], mx);
            const float corr = ex2(m_i[h] - mnew);
            m_i[h] = mnew;
            float rs = 0.0f;
#pragma unroll
            for (int nj = 0; nj < 4; nj++) {
                s[nj][2 * h]     = ex2(s[nj][2 * h] - mnew);
                s[nj][2 * h + 1] = ex2(s[nj][2 * h + 1] - mnew);
                rs += s[nj][2 * h] + s[nj][2 * h + 1];
            }
            rs += __shfl_xor_sync(0xffffffffu, rs, 1);
            rs += __shfl_xor_sync(0xffffffffu, rs, 2);
            l_i[h] = l_i[h] * corr + rs;
#pragma unroll
            for (int dj = 0; dj < 8; dj++) {
                o[dj][2 * h]     *= corr;
                o[dj][2 * h + 1] *= corr;
            }
        }

        // ---- P fragments (registers)
        unsigned pa[2][4];
#pragma unroll
        for (int cp = 0; cp < 2; cp++) {
            pa[cp][0] = pack2(s[2 * cp][0],     s[2 * cp][1]);
            pa[cp][1] = pack2(s[2 * cp][2],     s[2 * cp][3]);
            pa[cp][2] = pack2(s[2 * cp + 1][0], s[2 * cp + 1][1]);
            pa[cp][3] = pack2(s[2 * cp + 1][2], s[2 * cp + 1][3]);
        }

        // ---- O += P @ V
#pragma unroll
        for (int cp = 0; cp < 2; cp++) {
#pragma unroll
            for (int dj = 0; dj < 8; dj++) {
                const int d = dj * 8 + gp;
                const unsigned b0 = vb[d * 20 + 8 * cp + tg];
                const unsigned b1 = vb[d * 20 + 8 * cp + tg + 4];
                mma_f16(o[dj], pa[cp], b0, b1);
            }
        }
    }
#undef FISSUE

    // ---- write ctx natural fp16 [M, 512w]
    const int b_ = bh >> 4;
    const int hh = bh & 15;
#pragma unroll
    for (int h = 0; h < 2; h++) {
        const float inv = 1.0f / l_i[h];
        const int srow = q0 + qr0 + gp + 8 * h;
        unsigned* co = g_Ch + ((size_t)(b_ * S_ + srow) << 9) + (hh << 5);
#pragma unroll
        for (int dj = 0; dj < 8; dj++)
            co[4 * dj + tg] = pack2(o[dj][2 * h] * inv, o[dj][2 * h + 1] * inv);
    }
    (void)dummy;
}

// ---------------------------------------------------------------------------
extern "C" void kernel_launch(void* const* d_in, const int* in_sizes, int n_in,
                              void* d_out, int out_size)
{
    const float* query = (const float*)d_in[0];
    const float* key   = (const float*)d_in[1];
    const float* value = (const float*)d_in[2];
    const float* bq    = (const float*)d_in[4];
    const float* bk    = (const float*)d_in[6];
    const float* bv    = (const float*)d_in[8];
    const float* bo    = (const float*)d_in[10];
    const float* Wq    = (const float*)d_in[3];
    const float* Wk    = (const float*)d_in[5];
    const float* Wv    = (const float*)d_in[7];
    const float* Wo    = (const float*)d_in[9];

    static int smem_set = 0;
    if (!smem_set) {
        cudaFuncSetAttribute(qkv_gemm_kernel,
                             cudaFuncAttributeMaxDynamicSharedMemorySize, GM_SMEM);
        cudaFuncSetAttribute(out_gemm_kernel,
                             cudaFuncAttributeMaxDynamicSharedMemorySize, GM_SMEM);
        smem_set = 1;
    }

    convert_kernel<<<dim3(2048, 1, 7), 256>>>(query, key, value, Wq, Wk, Wv, Wo);

    qkv_gemm_kernel<<<dim3(D_ / 128, M_ / 128, 3), 128, GM_SMEM>>>(bq, bk, bv);

    flash_fp16_kernel<<<dim3(S_ / 128, B_ * H_), 256>>>((float*)d_out);

    out_gemm_kernel<<<dim3(D_ / 128, M_ / 128), 128, GM_SMEM>>>(bo, (float*)d_out);
}

// round 9
// speedup vs baseline: 8.6216x; 1.1169x over previous
#include <cuda_runtime.h>
#include <cuda_fp16.h>
#include <cstdint>

#define D_   1024
#define H_   16
#define HD_  64
#define B_   2
#define S_   2048
#define M_   (B_ * S_)          // 4096

// ---------------- scratch (device globals) ---------------------------------
__device__ unsigned g_q16[(size_t)M_ * D_ / 2];     // fp16 natural inputs
__device__ unsigned g_k16[(size_t)M_ * D_ / 2];
__device__ unsigned g_v16[(size_t)M_ * D_ / 2];
__device__ unsigned g_w16[4][(size_t)D_ * D_ / 2];  // Wq,Wk,Wv,Wo fp16
__device__ unsigned g_Qh[(size_t)M_ * D_ / 2];      // [B,H,S,32w] natural, *SC
__device__ unsigned g_Kh[(size_t)M_ * D_ / 2];      // [B,H,S,32w] natural
__device__ unsigned g_Vh[(size_t)M_ * D_ / 2];      // [B,H,64,S] perm along s
__device__ unsigned g_Ch[(size_t)M_ * D_ / 2];      // ctx [M,512w] natural

#define SC_Q 0.18033688011112042f   /* 0.125 * log2(e) */

// ---------------------------------------------------------------------------
// helpers
// ---------------------------------------------------------------------------
__device__ __forceinline__ unsigned pack2(float lo, float hi) {
    unsigned r;
    asm("cvt.rn.f16x2.f32 %0, %1, %2;" : "=r"(r) : "f"(hi), "f"(lo));
    return r;
}
__device__ __forceinline__ float ex2(float x) {
    float y; asm("ex2.approx.ftz.f32 %0, %1;" : "=f"(y) : "f"(x)); return y;
}
__device__ __forceinline__ void mma_f16(float c[4], const unsigned a[4], unsigned b0, unsigned b1) {
    asm volatile(
        "mma.sync.aligned.m16n8k16.row.col.f32.f16.f16.f32 "
        "{%0,%1,%2,%3}, {%4,%5,%6,%7}, {%8,%9}, {%0,%1,%2,%3};\n"
        : "+f"(c[0]), "+f"(c[1]), "+f"(c[2]), "+f"(c[3])
        : "r"(a[0]), "r"(a[1]), "r"(a[2]), "r"(a[3]), "r"(b0), "r"(b1));
}
__device__ __forceinline__ void ldsm4(unsigned& r0, unsigned& r1, unsigned& r2, unsigned& r3,
                                      unsigned addr) {
    asm volatile("ldmatrix.sync.aligned.m8n8.x4.shared.b16 {%0,%1,%2,%3}, [%4];"
                 : "=r"(r0), "=r"(r1), "=r"(r2), "=r"(r3) : "r"(addr));
}
#define CP16(dst, src) \
    asm volatile("cp.async.cg.shared.global [%0], [%1], 16;" :: "r"(dst), "l"(src) : "memory")
#define CP_COMMIT() asm volatile("cp.async.commit_group;" ::: "memory")
#define CP_WAIT1()  asm volatile("cp.async.wait_group 1;" ::: "memory")
#define CP_WAIT0()  asm volatile("cp.async.wait_group 0;" ::: "memory")

// ---------------------------------------------------------------------------
// convert: fp32 -> fp16 natural (q,k,v + 4 weights)
// ---------------------------------------------------------------------------
__global__ __launch_bounds__(256) void convert_kernel(
    const float* __restrict__ q, const float* __restrict__ k, const float* __restrict__ v,
    const float* __restrict__ wq, const float* __restrict__ wk,
    const float* __restrict__ wv, const float* __restrict__ wo)
{
    const int z = blockIdx.z;
    const float* src;
    unsigned* dst;
    size_t n;
    switch (z) {
        case 0: src = q;  dst = g_q16;    n = (size_t)M_ * D_; break;
        case 1: src = k;  dst = g_k16;    n = (size_t)M_ * D_; break;
        case 2: src = v;  dst = g_v16;    n = (size_t)M_ * D_; break;
        case 3: src = wq; dst = g_w16[0]; n = (size_t)D_ * D_; break;
        case 4: src = wk; dst = g_w16[1]; n = (size_t)D_ * D_; break;
        case 5: src = wv; dst = g_w16[2]; n = (size_t)D_ * D_; break;
        default: src = wo; dst = g_w16[3]; n = (size_t)D_ * D_; break;
    }
    const size_t i8 = ((size_t)blockIdx.x * blockDim.x + threadIdx.x) * 8;
    if (i8 >= n) return;
    float4 f0 = *(const float4*)(src + i8);
    float4 f1 = *(const float4*)(src + i8 + 4);
    uint4 o = make_uint4(pack2(f0.x, f0.y), pack2(f0.z, f0.w),
                         pack2(f1.x, f1.y), pack2(f1.z, f1.w));
    *(uint4*)(dst + i8 / 2) = o;
}

// ---------------------------------------------------------------------------
// fp16 GEMM: C[m,e] = A[m,:] . W[e,:] + bias[e]
// CTA 128x128, 128 threads (4 warps 2x2, warp tile 64x64), BK=64 halves,
// 3-stage cp.async, SW128 smem, ldmatrix fragments.
// modes: 0 float out [M,D]; 1 Q natural *SC; 2 K natural; 3 V transposed+perm
// ---------------------------------------------------------------------------
#define GSTG   3
#define TILEB  16384
#define GM_SMEM (GSTG * 2 * TILEB)   // 98304

__device__ __forceinline__ void gemm16_body(
    const unsigned* __restrict__ Aw,
    const unsigned* __restrict__ Ww,
    const float* __restrict__ bias,
    void* __restrict__ outp,
    int mode)
{
    extern __shared__ char smc[];
    const unsigned smA = (unsigned)__cvta_generic_to_shared(smc);
    const unsigned smB = smA + GSTG * TILEB;

    const int t    = threadIdx.x;
    const int lane = t & 31;
    const int w    = t >> 5;
    const int gp   = lane >> 2;
    const int tg   = lane & 3;
    const int wm0  = (w >> 1) << 6;
    const int wn0  = (w & 1) << 6;

    const int m0 = blockIdx.y << 7;
    const int n0 = blockIdx.x << 7;

    const unsigned* Ab = Aw + (size_t)m0 * 512;
    const unsigned* Bb = Ww + (size_t)n0 * 512;

    const int lr = t >> 3;
    const int lc = t & 7;

    const int la15 = lane & 15;
    const int ahi  = (lane >> 4) << 4;
    const int bsel = ((lane >> 3) & 1) << 4;
    const int brow0 = wn0 + ((lane >> 4) << 3) + (lane & 7);

    int arow[4], akey[4];
#pragma unroll
    for (int mi = 0; mi < 4; mi++) {
        const int r = wm0 + 16 * mi + la15;
        arow[mi] = 128 * r;
        akey[mi] = (r & 7) << 4;
    }

    float acc[4][8][4];
#pragma unroll
    for (int mi = 0; mi < 4; mi++)
#pragma unroll
        for (int nj = 0; nj < 8; nj++)
#pragma unroll
            for (int q = 0; q < 4; q++) acc[mi][nj][q] = 0.0f;

#define GISSUE(st, kc) do {                                                    \
    const unsigned da = smA + (st) * TILEB;                                    \
    const unsigned db = smB + (st) * TILEB;                                    \
    _Pragma("unroll")                                                          \
    for (int i = 0; i < 8; i++) {                                              \
        const int row = lr + 16 * i;                                           \
        const unsigned off = 128u * row + ((16u * lc) ^ ((row & 7) << 4));     \
        CP16(da + off, Ab + (size_t)row * 512 + (kc) * 32 + 4 * lc);           \
        CP16(db + off, Bb + (size_t)row * 512 + (kc) * 32 + 4 * lc);           \
    }                                                                          \
    CP_COMMIT();                                                               \
} while (0)

    GISSUE(0, 0);
    GISSUE(1, 1);

    for (int kc = 0; kc < 16; kc++) {
        if (kc == 15) { CP_WAIT0(); } else { CP_WAIT1(); }
        __syncthreads();
        if (kc + 2 < 16) {
            const int st = (kc + 2) % 3;
            GISSUE(st, kc + 2);
        }

        const unsigned ab = smA + (kc % 3) * TILEB;
        const unsigned bb = smB + (kc % 3) * TILEB;

#pragma unroll
        for (int s = 0; s < 4; s++) {
            unsigned a[4][4];
#pragma unroll
            for (int mi = 0; mi < 4; mi++) {
                const unsigned addr = ab + arow[mi] + ((32 * s + ahi) ^ akey[mi]);
                ldsm4(a[mi][0], a[mi][1], a[mi][2], a[mi][3], addr);
            }
#pragma unroll
            for (int nj2 = 0; nj2 < 4; nj2++) {
                const int row = brow0 + 16 * nj2;
                const unsigned addr = bb + 128u * row + ((32 * s + bsel) ^ ((row & 7) << 4));
                unsigned b0, b1, b2, b3;
                ldsm4(b0, b1, b2, b3, addr);
#pragma unroll
                for (int mi = 0; mi < 4; mi++) {
                    mma_f16(acc[mi][2 * nj2],     a[mi], b0, b1);
                    mma_f16(acc[mi][2 * nj2 + 1], a[mi], b2, b3);
                }
            }
        }
    }
#undef GISSUE

    // ---- epilogue
#pragma unroll
    for (int mi = 0; mi < 4; mi++) {
#pragma unroll
        for (int h = 0; h < 2; h++) {
            const int m  = m0 + wm0 + 16 * mi + gp + 8 * h;
            const int b_ = m >> 11;
            const int s  = m & (S_ - 1);
#pragma unroll
            for (int nj = 0; nj < 8; nj++) {
                const int e  = n0 + wn0 + 8 * nj + 2 * tg;
                const float vx = acc[mi][nj][2 * h]     + bias[e];
                const float vy = acc[mi][nj][2 * h + 1] + bias[e + 1];
                if (mode == 0) {
                    *(float2*)((float*)outp + (size_t)m * D_ + e) = make_float2(vx, vy);
                } else if (mode == 1 || mode == 2) {
                    const int hh = e >> 6, hd = e & 63;
                    const float sc = (mode == 1) ? SC_Q : 1.0f;
                    ((unsigned*)outp)[(((size_t)(b_ * H_ + hh) * S_ + s) << 5) + (hd >> 1)] =
                        pack2(vx * sc, vy * sc);
                } else {
                    // V: [b,h,hd][s] with per-16 s-word permutation:
                    // natural word w (u=w&3, v=w>>2) stored at 2u+v
                    const int hh = e >> 6, hd = e & 63;
                    const int g = s >> 4, z = s & 15;
                    const int sp = 16 * g + 4 * ((z >> 1) & 3) + 2 * ((z >> 3) & 1) + (z & 1);
                    __half* vo = (__half*)outp + (((size_t)(b_ * H_ + hh) * HD_ + hd)) * S_;
                    vo[sp]      = __float2half_rn(vx);
                    vo[S_ + sp] = __float2half_rn(vy);
                }
            }
        }
    }
}

__global__ __launch_bounds__(128, 2) void qkv_gemm_kernel(
    const float* __restrict__ bq, const float* __restrict__ bk, const float* __restrict__ bv)
{
    const int z = blockIdx.z;
    const unsigned* A = (z == 0) ? g_q16 : (z == 1) ? g_k16 : g_v16;
    const float* b    = (z == 0) ? bq : (z == 1) ? bk : bv;
    void* o           = (z == 0) ? (void*)g_Qh : (z == 1) ? (void*)g_Kh : (void*)g_Vh;
    gemm16_body(A, g_w16[z], b, o, z + 1);
}

__global__ __launch_bounds__(128, 2) void out_gemm_kernel(
    const float* __restrict__ bo, float* __restrict__ out)
{
    gemm16_body(g_Ch, g_w16[3], bo, (void*)out, 0);
}

// ---------------------------------------------------------------------------
// Flash attention fp16. 256 threads (8 warps), Q-tile 128 (16 rows/warp),
// K-tile 64, 3-stage cp.async, ldmatrix K frags, LDS.64 V frags,
// deferred l-sum, conditional rescale.
// K smem: SW128 64 rows x 128B (8192B/stage);
// V smem: 64 rows x 32 words used, stride 40 (10240B/stage).
// ---------------------------------------------------------------------------
#define FL_KSTG 8192
#define FL_VSTG 10240
#define FL_SMEM (3 * (FL_KSTG + FL_VSTG))   // 55296

__global__ __launch_bounds__(256, 2) void flash_fp16_kernel()
{
    extern __shared__ char fsm[];
    const unsigned smK = (unsigned)__cvta_generic_to_shared(fsm);
    const unsigned smV = smK + 3 * FL_KSTG;

    const int t    = threadIdx.x;
    const int lane = t & 31;
    const int w    = t >> 5;
    const int gp   = lane >> 2;
    const int tg   = lane & 3;
    const int qr0  = w << 4;

    const int bh = blockIdx.y;
    const int q0 = blockIdx.x << 7;

    const unsigned* Qw = g_Qh + (size_t)bh * S_ * 32;
    const unsigned* Kw = g_Kh + (size_t)bh * S_ * 32;
    const unsigned* Vw = g_Vh + (size_t)bh * HD_ * (S_ / 2);

    // loader mappings: 512 chunks each for K and V; 2 per thread
    const int kr0 = t >> 3;           // rows kr0, kr0+32
    const int kj  = t & 7;
    const unsigned koff0 = 128u * kr0 + ((16u * kj) ^ ((kr0 & 7) << 4));
    const unsigned koff1 = 128u * (kr0 + 32) + ((16u * kj) ^ (((kr0 + 32) & 7) << 4));
    const unsigned voff0 = 4u * (kr0 * 40 + 4 * kj);
    const unsigned voff1 = 4u * ((kr0 + 32) * 40 + 4 * kj);

#define FISSUE(st, it2) do {                                                     \
    const int kn = (it2) << 6;                                                   \
    CP16(smK + (st) * FL_KSTG + koff0, Kw + (size_t)(kn + kr0) * 32 + 4 * kj);   \
    CP16(smK + (st) * FL_KSTG + koff1, Kw + (size_t)(kn + kr0 + 32) * 32 + 4 * kj); \
    CP16(smV + (st) * FL_VSTG + voff0,                                           \
         Vw + (size_t)kr0 * (S_ / 2) + (it2) * 32 + 4 * kj);                     \
    CP16(smV + (st) * FL_VSTG + voff1,                                           \
         Vw + (size_t)(kr0 + 32) * (S_ / 2) + (it2) * 32 + 4 * kj);              \
    CP_COMMIT();                                                                 \
} while (0)

    // ---- Q fragments (natural layout, pre-scaled by SC_Q)
    unsigned qa[4][4];
#pragma unroll
    for (int s = 0; s < 4; s++) {
        const unsigned* r0 = Qw + (size_t)(q0 + qr0 + gp) * 32;
        const unsigned* r1 = Qw + (size_t)(q0 + qr0 + 8 + gp) * 32;
        qa[s][0] = r0[8 * s + tg];
        qa[s][1] = r1[8 * s + tg];
        qa[s][2] = r0[8 * s + tg + 4];
        qa[s][3] = r1[8 * s + tg + 4];
    }

    FISSUE(0, 0);
    FISSUE(1, 1);

    const int kbrow0 = ((lane >> 4) << 3) + (lane & 7);
    const int kbsel  = ((lane >> 3) & 1) << 4;

    float m_i[2] = {-1e30f, -1e30f};
    float l_i[2] = {0.0f, 0.0f};
    float o[8][4];
#pragma unroll
    for (int dj = 0; dj < 8; dj++)
#pragma unroll
        for (int q = 0; q < 4; q++) o[dj][q] = 0.0f;

    for (int it = 0; it < 32; it++) {
        if (it == 31) { CP_WAIT0(); } else { CP_WAIT1(); }
        __syncthreads();
        if (it + 2 < 32) FISSUE((it + 2) % 3, it + 2);

        const unsigned kb = smK + (it % 3) * FL_KSTG;
        const unsigned vb = smV + (it % 3) * FL_VSTG;

        // ---- S = Q K^T  (64 keys: s[8][4])
        float s[8][4];
#pragma unroll
        for (int nj = 0; nj < 8; nj++)
#pragma unroll
            for (int q = 0; q < 4; q++) s[nj][q] = 0.0f;

#pragma unroll
        for (int ks = 0; ks < 4; ks++) {
#pragma unroll
            for (int nj2 = 0; nj2 < 4; nj2++) {
                const int row = 16 * nj2 + kbrow0;
                const unsigned addr = kb + 128u * row + ((32 * ks + kbsel) ^ ((row & 7) << 4));
                unsigned b0, b1, b2, b3;
                ldsm4(b0, b1, b2, b3, addr);
                mma_f16(s[2 * nj2],     qa[ks], b0, b1);
                mma_f16(s[2 * nj2 + 1], qa[ks], b2, b3);
            }
        }

        // ---- online softmax (exp2 domain; deferred l-sum; cond. rescale)
#pragma unroll
        for (int h = 0; h < 2; h++) {
            float mx = fmaxf(s[0][2 * h], s[0][2 * h + 1]);
#pragma unroll
            for (int nj = 1; nj < 8; nj++)
                mx = fmaxf(mx, fmaxf(s[nj][2 * h], s[nj][2 * h + 1]));
            mx = fmaxf(mx, __shfl_xor_sync(0xffffffffu, mx, 1));
            mx = fmaxf(mx, __shfl_xor_sync(0xffffffffu, mx, 2));
            if (mx > m_i[h]) {                     // quad-uniform branch
                const float corr = ex2(m_i[h] - mx);
                m_i[h] = mx;
                l_i[h] *= corr;
#pragma unroll
                for (int dj = 0; dj < 8; dj++) {
                    o[dj][2 * h]     *= corr;
                    o[dj][2 * h + 1] *= corr;
                }
            }
            float rs = 0.0f;
#pragma unroll
            for (int nj = 0; nj < 8; nj++) {
                s[nj][2 * h]     = ex2(s[nj][2 * h] - m_i[h]);
                s[nj][2 * h + 1] = ex2(s[nj][2 * h + 1] - m_i[h]);
                rs += s[nj][2 * h] + s[nj][2 * h + 1];
            }
            l_i[h] += rs;                          // per-thread partial
        }

        // ---- P fragments
        unsigned pa[4][4];
#pragma unroll
        for (int cp = 0; cp < 4; cp++) {
            pa[cp][0] = pack2(s[2 * cp][0],     s[2 * cp][1]);
            pa[cp][1] = pack2(s[2 * cp][2],     s[2 * cp][3]);
            pa[cp][2] = pack2(s[2 * cp + 1][0], s[2 * cp + 1][1]);
            pa[cp][3] = pack2(s[2 * cp + 1][2], s[2 * cp + 1][3]);
        }

        // ---- O += P @ V (LDS.64 b-frags via permuted V words)
#pragma unroll
        for (int cp = 0; cp < 4; cp++) {
#pragma unroll
            for (int dj = 0; dj < 8; dj++) {
                const int d = dj * 8 + gp;
                uint2 bb = *(const uint2*)(fsm + (vb - smK) + 4u * (d * 40 + 8 * cp + 2 * tg));
                mma_f16(o[dj], pa[cp], bb.x, bb.y);
            }
        }
    }
#undef FISSUE

    // ---- finalize l (deferred quad sum), write ctx natural fp16
    const int b_ = bh >> 4;
    const int hh = bh & 15;
#pragma unroll
    for (int h = 0; h < 2; h++) {
        float l = l_i[h];
        l += __shfl_xor_sync(0xffffffffu, l, 1);
        l += __shfl_xor_sync(0xffffffffu, l, 2);
        const float inv = 1.0f / l;
        const int srow = q0 + qr0 + gp + 8 * h;
        unsigned* co = g_Ch + ((size_t)(b_ * S_ + srow) << 9) + (hh << 5);
#pragma unroll
        for (int dj = 0; dj < 8; dj++)
            co[4 * dj + tg] = pack2(o[dj][2 * h] * inv, o[dj][2 * h + 1] * inv);
    }
}

// ---------------------------------------------------------------------------
extern "C" void kernel_launch(void* const* d_in, const int* in_sizes, int n_in,
                              void* d_out, int out_size)
{
    const float* query = (const float*)d_in[0];
    const float* key   = (const float*)d_in[1];
    const float* value = (const float*)d_in[2];
    const float* Wq    = (const float*)d_in[3];
    const float* bq    = (const float*)d_in[4];
    const float* Wk    = (const float*)d_in[5];
    const float* bk    = (const float*)d_in[6];
    const float* Wv    = (const float*)d_in[7];
    const float* bv    = (const float*)d_in[8];
    const float* Wo    = (const float*)d_in[9];
    const float* bo    = (const float*)d_in[10];

    static int smem_set = 0;
    if (!smem_set) {
        cudaFuncSetAttribute(qkv_gemm_kernel,
                             cudaFuncAttributeMaxDynamicSharedMemorySize, GM_SMEM);
        cudaFuncSetAttribute(out_gemm_kernel,
                             cudaFuncAttributeMaxDynamicSharedMemorySize, GM_SMEM);
        cudaFuncSetAttribute(flash_fp16_kernel,
                             cudaFuncAttributeMaxDynamicSharedMemorySize, FL_SMEM);
        smem_set = 1;
    }

    convert_kernel<<<dim3(2048, 1, 7), 256>>>(query, key, value, Wq, Wk, Wv, Wo);

    qkv_gemm_kernel<<<dim3(D_ / 128, M_ / 128, 3), 128, GM_SMEM>>>(bq, bk, bv);

    flash_fp16_kernel<<<dim3(S_ / 128, B_ * H_), 256, FL_SMEM>>>();

    out_gemm_kernel<<<dim3(D_ / 128, M_ / 128), 128, GM_SMEM>>>(bo, (float*)d_out);
}